// round 1
// baseline (speedup 1.0000x reference)
#include <cuda_runtime.h>
#include <math.h>

// ---------------- problem constants ----------------
#define NNODE 6000
#define NEDGE 192000
#define DIM   512
#define NOUT  40
#define KC    4096

// ---------------- device scratch (static, no allocs) ----------------
__device__ float g_h  [NNODE * DIM];   // GraphConv1 output (post-relu)
__device__ float g_agg[NNODE * DIM];   // aggregation scratch (reused)
__device__ float g_hn [NNODE * DIM];   // l2norm(h)
__device__ float g_en [KC * DIM];      // l2norm(codebook)
__device__ float g_q  [NNODE * DIM];   // quantized (= en[ind])
__device__ float g_xe [NNODE * DIM];   // quantized_edge
__device__ float g_qn [NNODE * DIM];   // quantized_node
__device__ float g_h2 [NNODE * DIM];   // GraphConv2 output
__device__ float g_adjq[(size_t)NNODE * NNODE];  // 144 MB
__device__ int   g_cnt [(size_t)NNODE * NNODE];  // 144 MB, zero-init .bss, cleaned after use
__device__ int   g_dego[NNODE];
__device__ int   g_degi[NNODE];
__device__ float g_rso [NNODE];
__device__ float g_rsi [NNODE];
__device__ int   g_ind [NNODE];
__device__ double g_acc[8];            // 0:commit 1:node 2:sum_x 3:sum_x2 4:edge_sum_x 5:edge_sum_c
__device__ float g_min, g_max;

// ---------------- helpers ----------------
__device__ __forceinline__ void atomicMinF(float* a, float v) {
    int old = __float_as_int(*a);
    while (v < __int_as_float(old)) {
        int assumed = old;
        old = atomicCAS((int*)a, assumed, __float_as_int(v));
        if (old == assumed) break;
    }
}
__device__ __forceinline__ void atomicMaxF(float* a, float v) {
    int old = __float_as_int(*a);
    while (v > __int_as_float(old)) {
        int assumed = old;
        old = atomicCAS((int*)a, assumed, __float_as_int(v));
        if (old == assumed) break;
    }
}

// ---------------- generic tiled fp32 GEMM ----------------
// C[M,N] = op(A[M,K] (optionally row-scaled)) @ op(B) (+bias) (optional relu)
// TRANSB=false: B is [K,N] row-major. TRANSB=true: B is [N,K] row-major (C = A @ B^T).
template <bool TRANSB, bool RELU, bool BIAS>
__global__ void gemm_k(const float* __restrict__ A, const float* __restrict__ B,
                       const float* __restrict__ bias, float* __restrict__ C,
                       int M, int N, int K, const float* __restrict__ rowScale)
{
    __shared__ __align__(16) float As[16][64];
    __shared__ __align__(16) float Bs[16][64];

    const int tid = threadIdx.x;          // 256 threads
    const int bm = blockIdx.y * 64;
    const int bn = blockIdx.x * 64;
    const int ty = tid >> 4, tx = tid & 15;

    float acc[4][4];
#pragma unroll
    for (int i = 0; i < 4; i++)
#pragma unroll
        for (int j = 0; j < 4; j++) acc[i][j] = 0.f;

    const int ar = tid >> 2;              // 0..63 (A tile row)
    const int ac = (tid & 3) * 4;         // 0,4,8,12 (A tile k-col)
    const int gr = bm + ar;
    float ascale = 1.f;
    if (rowScale != nullptr && gr < M) ascale = rowScale[gr];

    for (int k0 = 0; k0 < K; k0 += 16) {
        // ---- load A tile (K is always a multiple of 16 & 4-aligned here) ----
        float4 av = make_float4(0.f, 0.f, 0.f, 0.f);
        if (gr < M) av = *(const float4*)(A + (size_t)gr * K + k0 + ac);
        As[ac + 0][ar] = av.x * ascale;
        As[ac + 1][ar] = av.y * ascale;
        As[ac + 2][ar] = av.z * ascale;
        As[ac + 3][ar] = av.w * ascale;

        // ---- load B tile ----
        if (TRANSB) {
            const int br = tid >> 2;          // n within tile 0..63
            const int bc = (tid & 3) * 4;     // k within tile
            const int gn = bn + br;
            float4 bv = make_float4(0.f, 0.f, 0.f, 0.f);
            if (gn < N) bv = *(const float4*)(B + (size_t)gn * K + k0 + bc);
            Bs[bc + 0][br] = bv.x;
            Bs[bc + 1][br] = bv.y;
            Bs[bc + 2][br] = bv.z;
            Bs[bc + 3][br] = bv.w;
        } else {
            const int br = tid >> 4;          // k within tile 0..15
            const int bc = (tid & 15) * 4;    // n within tile
            const int gn = bn + bc;
            float4 bv = make_float4(0.f, 0.f, 0.f, 0.f);
            const float* bp = B + (size_t)(k0 + br) * N;
            if (gn + 3 < N) {
                bv = *(const float4*)(bp + gn);
            } else {
                if (gn + 0 < N) bv.x = bp[gn + 0];
                if (gn + 1 < N) bv.y = bp[gn + 1];
                if (gn + 2 < N) bv.z = bp[gn + 2];
            }
            Bs[br][bc + 0] = bv.x;
            Bs[br][bc + 1] = bv.y;
            Bs[br][bc + 2] = bv.z;
            Bs[br][bc + 3] = bv.w;
        }
        __syncthreads();

#pragma unroll
        for (int k = 0; k < 16; k++) {
            float a[4], b[4];
            *(float4*)a = *(const float4*)&As[k][ty * 4];
            *(float4*)b = *(const float4*)&Bs[k][tx * 4];
#pragma unroll
            for (int i = 0; i < 4; i++)
#pragma unroll
                for (int j = 0; j < 4; j++)
                    acc[i][j] = fmaf(a[i], b[j], acc[i][j]);
        }
        __syncthreads();
    }

#pragma unroll
    for (int i = 0; i < 4; i++) {
        int gm = bm + ty * 4 + i;
        if (gm >= M) continue;
#pragma unroll
        for (int j = 0; j < 4; j++) {
            int gn = bn + tx * 4 + j;
            if (gn >= N) continue;
            float v = acc[i][j];
            if (BIAS) v += bias[gn];
            if (RELU) v = fmaxf(v, 0.f);
            C[(size_t)gm * N + gn] = v;
        }
    }
}

// ---------------- aux kernels ----------------
__global__ void k_init() {
    int t = threadIdx.x;
    if (t < 8) g_acc[t] = 0.0;
    if (t == 8) g_min = __int_as_float(0x7f800000);
    if (t == 9) g_max = __int_as_float(0xff800000);
}

__global__ void k_zero_deg() {
    int i = blockIdx.x * blockDim.x + threadIdx.x;
    if (i < NNODE) { g_dego[i] = 0; g_degi[i] = 0; }
}

__global__ void k_deg(const int* __restrict__ src, const int* __restrict__ dst) {
    int e = blockIdx.x * blockDim.x + threadIdx.x;
    if (e < NEDGE) {
        atomicAdd(&g_dego[src[e]], 1);
        atomicAdd(&g_degi[dst[e]], 1);
    }
}

__global__ void k_rsqrt_deg() {
    int i = blockIdx.x * blockDim.x + threadIdx.x;
    if (i < NNODE) {
        g_rso[i] = rsqrtf(fmaxf((float)g_dego[i], 1.f));
        g_rsi[i] = rsqrtf(fmaxf((float)g_degi[i], 1.f));
    }
}

__global__ void k_zero_agg() {
    const int tot = NNODE * DIM / 4;
    float4 z = make_float4(0.f, 0.f, 0.f, 0.f);
    for (int i = blockIdx.x * blockDim.x + threadIdx.x; i < tot; i += gridDim.x * blockDim.x)
        ((float4*)g_agg)[i] = z;
}

// agg[dst] += x[src] * rsqrt(deg_out[src]) : one block per edge, 128 threads
__global__ void k_scatter(const float* __restrict__ x, const int* __restrict__ src,
                          const int* __restrict__ dst) {
    int e = blockIdx.x;
    int s = src[e], d = dst[e];
    float rs = g_rso[s];
    const float4* xr = (const float4*)(x + (size_t)s * DIM);
    float* o = g_agg + (size_t)d * DIM;
    int i = threadIdx.x;                   // DIM/4 == 128 == blockDim
    float4 v = xr[i];
    atomicAdd(o + i * 4 + 0, v.x * rs);
    atomicAdd(o + i * 4 + 1, v.y * rs);
    atomicAdd(o + i * 4 + 2, v.z * rs);
    atomicAdd(o + i * 4 + 3, v.w * rs);
}

// row-wise L2 normalize (D=512), one block (128 thr) per row
__global__ void k_l2norm(const float* __restrict__ in, float* __restrict__ out) {
    int r = blockIdx.x;
    const float4* xi = (const float4*)(in + (size_t)r * DIM);
    float4* xo = (float4*)(out + (size_t)r * DIM);
    int t = threadIdx.x;
    float4 v = xi[t];
    float s = v.x * v.x + v.y * v.y + v.z * v.z + v.w * v.w;
    __shared__ float sh[128];
    sh[t] = s; __syncthreads();
    for (int o = 64; o > 0; o >>= 1) { if (t < o) sh[t] += sh[t + o]; __syncthreads(); }
    float inv = rsqrtf(sh[0] + 1e-12f);
    xo[t] = make_float4(v.x * inv, v.y * inv, v.z * inv, v.w * inv);
}

// first-occurrence argmax over K=4096, one block (256 thr) per node
__global__ void k_argmax(const float* __restrict__ dist) {
    int n = blockIdx.x;
    const float* row = dist + (size_t)n * KC;
    float best = -3.4e38f; int bi = KC;
    for (int j = threadIdx.x; j < KC; j += 256) {
        float v = row[j];
        if (v > best || (v == best && j < bi)) { best = v; bi = j; }
    }
    __shared__ float sv[256];
    __shared__ int   si[256];
    sv[threadIdx.x] = best; si[threadIdx.x] = bi; __syncthreads();
    for (int o = 128; o > 0; o >>= 1) {
        if (threadIdx.x < o) {
            float v2 = sv[threadIdx.x + o]; int i2 = si[threadIdx.x + o];
            if (v2 > sv[threadIdx.x] || (v2 == sv[threadIdx.x] && i2 < si[threadIdx.x])) {
                sv[threadIdx.x] = v2; si[threadIdx.x] = i2;
            }
        }
        __syncthreads();
    }
    if (threadIdx.x == 0) g_ind[n] = si[0];
}

__device__ __forceinline__ double blockReduceD(double v, double* sh) {
    int t = threadIdx.x;
    sh[t] = v; __syncthreads();
    for (int o = blockDim.x / 2; o > 0; o >>= 1) {
        if (t < o) sh[t] += sh[t + o];
        __syncthreads();
    }
    return sh[0];
}

// q = en[ind], commit partial sum; one block (128 thr) per node
__global__ void k_gather_commit() {
    int n = blockIdx.x;
    int idx = g_ind[n];
    const float4* e = (const float4*)(g_en + (size_t)idx * DIM);
    const float4* h = (const float4*)(g_h + (size_t)n * DIM);
    float4* q = (float4*)(g_q + (size_t)n * DIM);
    int t = threadIdx.x;
    float4 ev = e[t], hv = h[t];
    q[t] = ev;
    float dx = ev.x - hv.x, dy = ev.y - hv.y, dz = ev.z - hv.z, dw = ev.w - hv.w;
    double s = (double)dx * dx + (double)dy * dy + (double)dz * dz + (double)dw * dw;
    __shared__ double sh[128];
    double tot = blockReduceD(s, sh);
    if (t == 0) atomicAdd(&g_acc[0], tot);
}

__global__ void k_nodeloss() {
    const int tot = NNODE * DIM;
    double s = 0.0;
    for (int i = blockIdx.x * blockDim.x + threadIdx.x; i < tot; i += gridDim.x * blockDim.x) {
        float d = g_h[i] - g_qn[i];
        s += (double)d * d;
    }
    __shared__ double sh[256];
    double b = blockReduceD(s, sh);
    if (threadIdx.x == 0) atomicAdd(&g_acc[1], b);
}

// streaming stats over adj_q: min, max, sum, sum of squares
__global__ void k_stats() {
    const size_t tot = (size_t)NNODE * NNODE / 4;
    const float4* a = (const float4*)g_adjq;
    float mn = 3.4e38f, mx = -3.4e38f;
    double s = 0.0, s2 = 0.0;
    for (size_t i = blockIdx.x * (size_t)blockDim.x + threadIdx.x; i < tot;
         i += (size_t)gridDim.x * blockDim.x) {
        float4 v = a[i];
        mn = fminf(mn, fminf(fminf(v.x, v.y), fminf(v.z, v.w)));
        mx = fmaxf(mx, fmaxf(fmaxf(v.x, v.y), fmaxf(v.z, v.w)));
        s  += (double)v.x + (double)v.y + (double)v.z + (double)v.w;
        s2 += (double)v.x * v.x + (double)v.y * v.y + (double)v.z * v.z + (double)v.w * v.w;
    }
    __shared__ double shd[256];
    __shared__ float  shm[256];
    double bs = blockReduceD(s, shd);
    if (threadIdx.x == 0) atomicAdd(&g_acc[2], bs);
    __syncthreads();
    double bs2 = blockReduceD(s2, shd);
    if (threadIdx.x == 0) atomicAdd(&g_acc[3], bs2);
    __syncthreads();
    // min
    shm[threadIdx.x] = mn; __syncthreads();
    for (int o = 128; o > 0; o >>= 1) {
        if (threadIdx.x < o) shm[threadIdx.x] = fminf(shm[threadIdx.x], shm[threadIdx.x + o]);
        __syncthreads();
    }
    if (threadIdx.x == 0) atomicMinF(&g_min, shm[0]);
    __syncthreads();
    // max
    shm[threadIdx.x] = mx; __syncthreads();
    for (int o = 128; o > 0; o >>= 1) {
        if (threadIdx.x < o) shm[threadIdx.x] = fmaxf(shm[threadIdx.x], shm[threadIdx.x + o]);
        __syncthreads();
    }
    if (threadIdx.x == 0) atomicMaxF(&g_max, shm[0]);
}

__global__ void k_cnt_inc(const int* __restrict__ src, const int* __restrict__ dst) {
    int e = blockIdx.x * blockDim.x + threadIdx.x;
    if (e < NEDGE) atomicAdd(&g_cnt[(size_t)dst[e] * NNODE + src[e]], 1);
}

__global__ void k_edge_sum(const int* __restrict__ src, const int* __restrict__ dst) {
    double sx = 0.0, sc = 0.0;
    for (int e = blockIdx.x * blockDim.x + threadIdx.x; e < NEDGE; e += gridDim.x * blockDim.x) {
        size_t idx = (size_t)dst[e] * NNODE + src[e];
        sx += (double)g_adjq[idx];
        sc += (double)g_cnt[idx];
    }
    __shared__ double sh[256];
    double bx = blockReduceD(sx, sh);
    if (threadIdx.x == 0) atomicAdd(&g_acc[4], bx);
    __syncthreads();
    double bc = blockReduceD(sc, sh);
    if (threadIdx.x == 0) atomicAdd(&g_acc[5], bc);
}

__global__ void k_cnt_clear(const int* __restrict__ src, const int* __restrict__ dst) {
    int e = blockIdx.x * blockDim.x + threadIdx.x;
    if (e < NEDGE) g_cnt[(size_t)dst[e] * NNODE + src[e]] = 0;
}

__global__ void k_final(float* __restrict__ loss) {
    double nd = (double)NNODE * DIM;
    double commit = 0.25 * g_acc[0] / nd;
    double nodeL  = g_acc[1] / nd;
    double mn = (double)g_min, mx = (double)g_max;
    double inv = 1.0 / (mx - mn);
    double NN = (double)NNODE * (double)NNODE;
    // sum over all entries of a^2, a=(x-mn)*inv
    double Sa2 = inv * inv * (g_acc[3] - 2.0 * mn * g_acc[2] + NN * mn * mn);
    // sum over edge list (with multiplicity) of a at edge positions = sum_distinct c*a
    double Sea = inv * (g_acc[4] - (double)NEDGE * mn);
    // sum_distinct c^2 = sum over edge list of c
    double tot = Sa2 - 2.0 * Sea + g_acc[5];
    double edgeL = sqrt(tot / NN);
    *loss = (float)(nodeL + edgeL + commit);
}

// ---------------- launch ----------------
extern "C" void kernel_launch(void* const* d_in, const int* in_sizes, int n_in,
                              void* d_out, int out_size) {
    (void)in_sizes; (void)n_in; (void)out_size;
    const float* feats = (const float*)d_in[0];
    const float* W1  = (const float*)d_in[1];
    const float* b1  = (const float*)d_in[2];
    const float* W2  = (const float*)d_in[3];
    const float* b2  = (const float*)d_in[4];
    const float* Wd1 = (const float*)d_in[5];
    const float* bd1 = (const float*)d_in[6];
    const float* Wd2 = (const float*)d_in[7];
    const float* bd2 = (const float*)d_in[8];
    const float* Wl  = (const float*)d_in[9];
    const float* bl  = (const float*)d_in[10];
    const float* cb  = (const float*)d_in[11];
    const int* src   = (const int*)d_in[12];
    const int* dst   = (const int*)d_in[13];

    float* out  = (float*)d_out;                 // [N, O]
    float* loss = out + (size_t)NNODE * NOUT;    // scalar
    float* dist = loss + 1;                      // [N, K]

    float *p_h, *p_agg, *p_hn, *p_en, *p_q, *p_xe, *p_qn, *p_h2, *p_adjq, *p_rsi;
    cudaGetSymbolAddress((void**)&p_h,   g_h);
    cudaGetSymbolAddress((void**)&p_agg, g_agg);
    cudaGetSymbolAddress((void**)&p_hn,  g_hn);
    cudaGetSymbolAddress((void**)&p_en,  g_en);
    cudaGetSymbolAddress((void**)&p_q,   g_q);
    cudaGetSymbolAddress((void**)&p_xe,  g_xe);
    cudaGetSymbolAddress((void**)&p_qn,  g_qn);
    cudaGetSymbolAddress((void**)&p_h2,  g_h2);
    cudaGetSymbolAddress((void**)&p_adjq, g_adjq);
    cudaGetSymbolAddress((void**)&p_rsi, g_rsi);

    #define GEMM_GRID(M, N) dim3(((N) + 63) / 64, ((M) + 63) / 64)

    k_init<<<1, 32>>>();
    k_zero_deg<<<(NNODE + 255) / 256, 256>>>();
    k_deg<<<(NEDGE + 255) / 256, 256>>>(src, dst);
    k_rsqrt_deg<<<(NNODE + 255) / 256, 256>>>();

    // GraphConv 1
    k_zero_agg<<<512, 256>>>();
    k_scatter<<<NEDGE, 128>>>(feats, src, dst);
    gemm_k<false, true, true><<<GEMM_GRID(NNODE, DIM), 256>>>(
        p_agg, W1, b1, p_h, NNODE, DIM, DIM, p_rsi);

    // VQ: cosine distances + argmax + gather + commit loss
    k_l2norm<<<KC, 128>>>(cb, p_en);
    k_l2norm<<<NNODE, 128>>>(p_h, p_hn);
    gemm_k<true, false, false><<<GEMM_GRID(NNODE, KC), 256>>>(
        p_hn, p_en, nullptr, dist, NNODE, KC, DIM, nullptr);
    k_argmax<<<NNODE, 256>>>(dist);
    k_gather_commit<<<NNODE, 128>>>();

    // decoders
    gemm_k<false, false, true><<<GEMM_GRID(NNODE, DIM), 256>>>(
        p_q, Wd1, bd1, p_xe, NNODE, DIM, DIM, nullptr);
    gemm_k<false, false, true><<<GEMM_GRID(NNODE, DIM), 256>>>(
        p_q, Wd2, bd2, p_qn, NNODE, DIM, DIM, nullptr);
    k_nodeloss<<<512, 256>>>();

    // adjacency reconstruction
    gemm_k<true, false, false><<<GEMM_GRID(NNODE, NNODE), 256>>>(
        p_xe, p_xe, nullptr, p_adjq, NNODE, NNODE, DIM, nullptr);
    k_stats<<<2048, 256>>>();
    k_cnt_inc<<<(NEDGE + 255) / 256, 256>>>(src, dst);
    k_edge_sum<<<256, 256>>>(src, dst);
    k_cnt_clear<<<(NEDGE + 255) / 256, 256>>>(src, dst);

    // GraphConv 2 + output head
    k_zero_agg<<<512, 256>>>();
    k_scatter<<<NEDGE, 128>>>(p_xe, src, dst);
    gemm_k<false, true, true><<<GEMM_GRID(NNODE, DIM), 256>>>(
        p_agg, W2, b2, p_h2, NNODE, DIM, DIM, p_rsi);
    gemm_k<false, false, true><<<GEMM_GRID(NNODE, NOUT), 256>>>(
        p_h2, Wl, bl, out, NNODE, NOUT, DIM, nullptr);

    k_final<<<1, 1>>>(loss);
    #undef GEMM_GRID
}

// round 3
// speedup vs baseline: 2.1283x; 2.1283x over previous
#include <cuda_runtime.h>
#include <math.h>
#include <float.h>

// ---------------- problem constants ----------------
#define NNODE 6000
#define NEDGE 192000
#define DIM   512
#define NOUT  40
#define KC    4096

// ---------------- device scratch ----------------
__device__ float g_h  [NNODE * DIM];
__device__ float g_agg[NNODE * DIM];
__device__ float g_hn [NNODE * DIM];
__device__ float g_en [KC * DIM];
__device__ float g_q  [NNODE * DIM];
__device__ float g_xe [NNODE * DIM];
__device__ float g_qn [NNODE * DIM];
__device__ float g_h2 [NNODE * DIM];
__device__ float g_adjq[(size_t)NNODE * NNODE];
__device__ int   g_cnt [(size_t)NNODE * NNODE];   // zero-init, cleaned after use
__device__ int   g_dego[NNODE];
__device__ int   g_degi[NNODE];
__device__ float g_rso [NNODE];
__device__ float g_rsi [NNODE];
__device__ int   g_ind [NNODE];
__device__ int   g_rowptr[NNODE + 1];
__device__ int   g_cur [NNODE];
__device__ int   g_srcs[NEDGE];
__device__ double g_acc[8];   // 0:commit 1:node 2:sum_x 3:sum_x2 4:edge_sum_x 5:edge_sum_c
__device__ float g_min, g_max;

// ---------------- helpers ----------------
__device__ __forceinline__ void atomicMinF(float* a, float v) {
    int old = __float_as_int(*a);
    while (v < __int_as_float(old)) {
        int assumed = old;
        old = atomicCAS((int*)a, assumed, __float_as_int(v));
        if (old == assumed) break;
    }
}
__device__ __forceinline__ void atomicMaxF(float* a, float v) {
    int old = __float_as_int(*a);
    while (v > __int_as_float(old)) {
        int assumed = old;
        old = atomicCAS((int*)a, assumed, __float_as_int(v));
        if (old == assumed) break;
    }
}
__device__ __forceinline__ unsigned f2tf(float f) {
    unsigned u;
    asm("cvt.rna.tf32.f32 %0, %1;" : "=r"(u) : "f"(f));
    return u;
}
__device__ __forceinline__ void mma_tf32(float c[4], unsigned a0, unsigned a1,
                                         unsigned a2, unsigned a3,
                                         unsigned b0, unsigned b1) {
    asm volatile(
        "mma.sync.aligned.m16n8k8.row.col.f32.tf32.tf32.f32 "
        "{%0,%1,%2,%3}, {%4,%5,%6,%7}, {%8,%9}, {%0,%1,%2,%3};\n"
        : "+f"(c[0]), "+f"(c[1]), "+f"(c[2]), "+f"(c[3])
        : "r"(a0), "r"(a1), "r"(a2), "r"(a3), "r"(b0), "r"(b1));
}

// ================= TF32 tensor-core GEMM =================
// C[M,N] = A[M,K] @ op(B) (+bias) (relu) (stats epilogue)
// TRANSB=true: B is [N,K] row-major (C = A @ B^T). false: B is [K,N] row-major.
// SPLIT=true: 3xTF32 split precision (fp32-grade accuracy).
// Tiles: BM=BN=128, BK=16, single smem stage, 256 threads = 8 warps (2m x 4n).
template <bool TRANSB, bool RELU, bool BIAS, bool STATS, bool SPLIT>
__global__ void __launch_bounds__(256) tgemm(
    const float* __restrict__ A, const float* __restrict__ B,
    const float* __restrict__ bias, float* __restrict__ C,
    int M, int N, int K)
{
    constexpr int AW = 128 * 20;                    // words per A buffer
    constexpr int BW = TRANSB ? 128 * 20 : 16 * 132;
    constexpr int NBUF = SPLIT ? 2 : 1;
    constexpr int WORDS = NBUF * (AW + BW);
    __shared__ __align__(16) unsigned sm[WORDS < 768 ? 768 : WORDS];

    unsigned* Ah = sm;                     // A hi: [128][20]
    unsigned* Al = sm + AW;                // A lo (SPLIT only)
    unsigned* Bh = sm + NBUF * AW;         // B hi
    unsigned* Bl = Bh + BW;                // B lo (SPLIT only)

    const int tid  = threadIdx.x;
    const int warp = tid >> 5, lane = tid & 31;
    const int g    = lane >> 2, c4 = lane & 3;
    const int wm   = (warp & 1) * 64, wn = (warp >> 1) * 32;
    const int bm   = blockIdx.y * 128, bn = blockIdx.x * 128;

    float acc[4][4][4];
#pragma unroll
    for (int i = 0; i < 4; i++)
#pragma unroll
        for (int j = 0; j < 4; j++)
#pragma unroll
            for (int r = 0; r < 4; r++) acc[i][j][r] = 0.f;

    float4 arv[2], brv[2];

    auto ldg_stage = [&](int k0) {
#pragma unroll
        for (int p = 0; p < 2; p++) {
            int idx = p * 256 + tid;
            int r = idx >> 2, kc = (idx & 3) * 4;
            int gr = bm + r;
            arv[p] = (gr < M) ? *(const float4*)(A + (size_t)gr * K + k0 + kc)
                              : make_float4(0.f, 0.f, 0.f, 0.f);
        }
        if (TRANSB) {
#pragma unroll
            for (int p = 0; p < 2; p++) {
                int idx = p * 256 + tid;
                int r = idx >> 2, kc = (idx & 3) * 4;
                int gn = bn + r;
                brv[p] = (gn < N) ? *(const float4*)(B + (size_t)gn * K + k0 + kc)
                                  : make_float4(0.f, 0.f, 0.f, 0.f);
            }
        } else {
#pragma unroll
            for (int p = 0; p < 2; p++) {
                int idx = p * 256 + tid;
                int kr = idx >> 5, nc = (idx & 31) * 4;
                int col = bn + nc;
                const float* bp = B + (size_t)(k0 + kr) * N;
                float4 v = make_float4(0.f, 0.f, 0.f, 0.f);
                if (col + 3 < N) v = *(const float4*)(bp + col);
                else {
                    if (col + 0 < N) v.x = bp[col + 0];
                    if (col + 1 < N) v.y = bp[col + 1];
                    if (col + 2 < N) v.z = bp[col + 2];
                }
                brv[p] = v;
            }
        }
    };

    auto cvt_store = [&](const float4& v, unsigned* hi, unsigned* lo, int off) {
        unsigned hx = f2tf(v.x), hy = f2tf(v.y), hz = f2tf(v.z), hw = f2tf(v.w);
        *(uint4*)(hi + off) = make_uint4(hx, hy, hz, hw);
        if (SPLIT) {
            unsigned lx = f2tf(v.x - __uint_as_float(hx));
            unsigned ly = f2tf(v.y - __uint_as_float(hy));
            unsigned lz = f2tf(v.z - __uint_as_float(hz));
            unsigned lw = f2tf(v.w - __uint_as_float(hw));
            *(uint4*)(lo + off) = make_uint4(lx, ly, lz, lw);
        }
    };

    auto sts_stage = [&]() {
#pragma unroll
        for (int p = 0; p < 2; p++) {
            int idx = p * 256 + tid;
            int r = idx >> 2, kc = (idx & 3) * 4;
            cvt_store(arv[p], Ah, Al, r * 20 + kc);
        }
#pragma unroll
        for (int p = 0; p < 2; p++) {
            int idx = p * 256 + tid;
            if (TRANSB) {
                int r = idx >> 2, kc = (idx & 3) * 4;
                cvt_store(brv[p], Bh, Bl, r * 20 + kc);
            } else {
                int kr = idx >> 5, nc = (idx & 31) * 4;
                cvt_store(brv[p], Bh, Bl, kr * 132 + nc);
            }
        }
    };

    auto compute = [&]() {
#pragma unroll
        for (int kk = 0; kk < 16; kk += 8) {
            unsigned ah[4][4], al[4][4], bh[4][2], bl[4][2];
#pragma unroll
            for (int mt = 0; mt < 4; mt++) {
                int row = wm + mt * 16 + g;
                ah[mt][0] = Ah[row * 20 + kk + c4];
                ah[mt][1] = Ah[(row + 8) * 20 + kk + c4];
                ah[mt][2] = Ah[row * 20 + kk + c4 + 4];
                ah[mt][3] = Ah[(row + 8) * 20 + kk + c4 + 4];
                if (SPLIT) {
                    al[mt][0] = Al[row * 20 + kk + c4];
                    al[mt][1] = Al[(row + 8) * 20 + kk + c4];
                    al[mt][2] = Al[row * 20 + kk + c4 + 4];
                    al[mt][3] = Al[(row + 8) * 20 + kk + c4 + 4];
                }
            }
#pragma unroll
            for (int nt = 0; nt < 4; nt++) {
                int col = wn + nt * 8 + g;
                if (TRANSB) {
                    bh[nt][0] = Bh[col * 20 + kk + c4];
                    bh[nt][1] = Bh[col * 20 + kk + c4 + 4];
                    if (SPLIT) {
                        bl[nt][0] = Bl[col * 20 + kk + c4];
                        bl[nt][1] = Bl[col * 20 + kk + c4 + 4];
                    }
                } else {
                    bh[nt][0] = Bh[(kk + c4) * 132 + col];
                    bh[nt][1] = Bh[(kk + c4 + 4) * 132 + col];
                    if (SPLIT) {
                        bl[nt][0] = Bl[(kk + c4) * 132 + col];
                        bl[nt][1] = Bl[(kk + c4 + 4) * 132 + col];
                    }
                }
            }
#pragma unroll
            for (int mt = 0; mt < 4; mt++)
#pragma unroll
                for (int nt = 0; nt < 4; nt++) {
                    mma_tf32(acc[mt][nt], ah[mt][0], ah[mt][1], ah[mt][2], ah[mt][3],
                             bh[nt][0], bh[nt][1]);
                    if (SPLIT) {
                        mma_tf32(acc[mt][nt], ah[mt][0], ah[mt][1], ah[mt][2], ah[mt][3],
                                 bl[nt][0], bl[nt][1]);
                        mma_tf32(acc[mt][nt], al[mt][0], al[mt][1], al[mt][2], al[mt][3],
                                 bh[nt][0], bh[nt][1]);
                    }
                }
        }
    };

    const int KT = K / 16;
    ldg_stage(0);
    for (int kt = 0; kt < KT; ++kt) {
        sts_stage();
        __syncthreads();
        if (kt + 1 < KT) ldg_stage((kt + 1) * 16);
        compute();
        __syncthreads();
    }

    // ---- epilogue (scalar stores: C may be only 4-byte aligned) ----
    float  lmn = FLT_MAX, lmx = -FLT_MAX;
    double ls = 0.0, ls2 = 0.0;
#pragma unroll
    for (int mt = 0; mt < 4; mt++) {
#pragma unroll
        for (int nt = 0; nt < 4; nt++) {
            int col = bn + wn + nt * 8 + 2 * c4;
            bool ok0 = col < N, ok1 = col + 1 < N;
            float bias0 = 0.f, bias1 = 0.f;
            if (BIAS) { if (ok0) bias0 = bias[col]; if (ok1) bias1 = bias[col + 1]; }
#pragma unroll
            for (int half = 0; half < 2; half++) {
                int rr = bm + wm + mt * 16 + g + 8 * half;
                if (rr >= M) continue;
                float v0 = acc[mt][nt][half * 2 + 0] + bias0;
                float v1 = acc[mt][nt][half * 2 + 1] + bias1;
                if (RELU) { v0 = fmaxf(v0, 0.f); v1 = fmaxf(v1, 0.f); }
                if (ok0) C[(size_t)rr * N + col] = v0;
                if (ok1) C[(size_t)rr * N + col + 1] = v1;
                if (STATS) {
                    if (ok0) {
                        lmn = fminf(lmn, v0); lmx = fmaxf(lmx, v0);
                        ls += (double)v0; ls2 += (double)v0 * v0;
                    }
                    if (ok1) {
                        lmn = fminf(lmn, v1); lmx = fmaxf(lmx, v1);
                        ls += (double)v1; ls2 += (double)v1 * v1;
                    }
                }
            }
        }
    }

    if (STATS) {
        __syncthreads();
        double* rb = (double*)sm;
        rb[tid] = ls; __syncthreads();
        for (int o = 128; o > 0; o >>= 1) { if (tid < o) rb[tid] += rb[tid + o]; __syncthreads(); }
        if (tid == 0) atomicAdd(&g_acc[2], rb[0]);
        __syncthreads();
        rb[tid] = ls2; __syncthreads();
        for (int o = 128; o > 0; o >>= 1) { if (tid < o) rb[tid] += rb[tid + o]; __syncthreads(); }
        if (tid == 0) atomicAdd(&g_acc[3], rb[0]);
        __syncthreads();
        float* fb = (float*)sm;
        fb[tid] = lmn; __syncthreads();
        for (int o = 128; o > 0; o >>= 1) { if (tid < o) fb[tid] = fminf(fb[tid], fb[tid + o]); __syncthreads(); }
        if (tid == 0) atomicMinF(&g_min, fb[0]);
        __syncthreads();
        fb[tid] = lmx; __syncthreads();
        for (int o = 128; o > 0; o >>= 1) { if (tid < o) fb[tid] = fmaxf(fb[tid], fb[tid + o]); __syncthreads(); }
        if (tid == 0) atomicMaxF(&g_max, fb[0]);
    }
}

// ================= fp32 SIMT GEMM (head only, N=40) =================
__global__ void gemm_head(const float* __restrict__ A, const float* __restrict__ B,
                          const float* __restrict__ bias, float* __restrict__ C,
                          int M, int N, int K)
{
    __shared__ __align__(16) float As[16][64];
    __shared__ __align__(16) float Bs[16][64];
    const int tid = threadIdx.x;
    const int bm = blockIdx.y * 64, bn = blockIdx.x * 64;
    const int ty = tid >> 4, tx = tid & 15;
    float acc[4][4];
#pragma unroll
    for (int i = 0; i < 4; i++)
#pragma unroll
        for (int j = 0; j < 4; j++) acc[i][j] = 0.f;

    const int ar = tid >> 2, ac = (tid & 3) * 4;
    const int gr = bm + ar;
    for (int k0 = 0; k0 < K; k0 += 16) {
        float4 av = make_float4(0.f, 0.f, 0.f, 0.f);
        if (gr < M) av = *(const float4*)(A + (size_t)gr * K + k0 + ac);
        As[ac + 0][ar] = av.x; As[ac + 1][ar] = av.y;
        As[ac + 2][ar] = av.z; As[ac + 3][ar] = av.w;

        const int br = tid >> 4, bc = (tid & 15) * 4;
        const int gn = bn + bc;
        float4 bv = make_float4(0.f, 0.f, 0.f, 0.f);
        const float* bp = B + (size_t)(k0 + br) * N;
        if (gn + 3 < N) bv = *(const float4*)(bp + gn);
        else {
            if (gn + 0 < N) bv.x = bp[gn + 0];
            if (gn + 1 < N) bv.y = bp[gn + 1];
            if (gn + 2 < N) bv.z = bp[gn + 2];
        }
        Bs[br][bc + 0] = bv.x; Bs[br][bc + 1] = bv.y;
        Bs[br][bc + 2] = bv.z; Bs[br][bc + 3] = bv.w;
        __syncthreads();
#pragma unroll
        for (int k = 0; k < 16; k++) {
            float a[4], b[4];
            *(float4*)a = *(const float4*)&As[k][ty * 4];
            *(float4*)b = *(const float4*)&Bs[k][tx * 4];
#pragma unroll
            for (int i = 0; i < 4; i++)
#pragma unroll
                for (int j = 0; j < 4; j++) acc[i][j] = fmaf(a[i], b[j], acc[i][j]);
        }
        __syncthreads();
    }
#pragma unroll
    for (int i = 0; i < 4; i++) {
        int gm = bm + ty * 4 + i;
        if (gm >= M) continue;
#pragma unroll
        for (int j = 0; j < 4; j++) {
            int gn = bn + tx * 4 + j;
            if (gn >= N) continue;
            C[(size_t)gm * N + gn] = acc[i][j] + bias[gn];
        }
    }
}

// ---------------- aux kernels ----------------
__global__ void k_init() {
    int t = threadIdx.x;
    if (t < 8) g_acc[t] = 0.0;
    if (t == 8) g_min = __int_as_float(0x7f800000);
    if (t == 9) g_max = __int_as_float(0xff800000);
}

__global__ void k_zero_deg() {
    int i = blockIdx.x * blockDim.x + threadIdx.x;
    if (i < NNODE) { g_dego[i] = 0; g_degi[i] = 0; }
}

__global__ void k_deg(const int* __restrict__ src, const int* __restrict__ dst) {
    int e = blockIdx.x * blockDim.x + threadIdx.x;
    if (e < NEDGE) {
        atomicAdd(&g_dego[src[e]], 1);
        atomicAdd(&g_degi[dst[e]], 1);
    }
}

__global__ void k_rsqrt_deg() {
    int i = blockIdx.x * blockDim.x + threadIdx.x;
    if (i < NNODE) {
        g_rso[i] = rsqrtf(fmaxf((float)g_dego[i], 1.f));
        g_rsi[i] = rsqrtf(fmaxf((float)g_degi[i], 1.f));
    }
}

// single-block scan over in-degrees -> CSR row pointers
__global__ void k_scan() {
    __shared__ int part[1024];
    int t = threadIdx.x;
    int base = t * 6;
    int loc[6]; int s = 0;
#pragma unroll
    for (int i = 0; i < 6; i++) {
        int idx = base + i; loc[i] = s;
        if (idx < NNODE) s += g_degi[idx];
    }
    part[t] = s; __syncthreads();
    for (int off = 1; off < 1024; off <<= 1) {
        int v = (t >= off) ? part[t - off] : 0;
        __syncthreads();
        part[t] += v;
        __syncthreads();
    }
    int pre = (t > 0) ? part[t - 1] : 0;
#pragma unroll
    for (int i = 0; i < 6; i++) {
        int idx = base + i;
        if (idx < NNODE) { g_rowptr[idx] = pre + loc[i]; g_cur[idx] = pre + loc[i]; }
    }
    if (t == 0) g_rowptr[NNODE] = NEDGE;
}

__global__ void k_fill(const int* __restrict__ src, const int* __restrict__ dst) {
    int e = blockIdx.x * blockDim.x + threadIdx.x;
    if (e < NEDGE) {
        int p = atomicAdd(&g_cur[dst[e]], 1);
        g_srcs[p] = src[e];
    }
}

// CSR gather-aggregate: out[n] = rsi[n] * sum_{e in in(n)} x[src(e)] * rso[src(e)]
__global__ void k_aggregate(const float* __restrict__ x, float* __restrict__ o) {
    int n = blockIdx.x, t = threadIdx.x;   // 128 threads, DIM/4 = 128
    int beg = g_rowptr[n], end = g_rowptr[n + 1];
    float ax = 0.f, ay = 0.f, az = 0.f, aw = 0.f;
    for (int e = beg; e < end; e++) {
        int s = g_srcs[e];
        float rs = g_rso[s];
        float4 v = ((const float4*)x)[(size_t)s * 128 + t];
        ax = fmaf(v.x, rs, ax); ay = fmaf(v.y, rs, ay);
        az = fmaf(v.z, rs, az); aw = fmaf(v.w, rs, aw);
    }
    float ri = g_rsi[n];
    ((float4*)o)[(size_t)n * 128 + t] = make_float4(ax * ri, ay * ri, az * ri, aw * ri);
}

// row-wise L2 normalize (D=512)
__global__ void k_l2norm(const float* __restrict__ in, float* __restrict__ out) {
    int r = blockIdx.x;
    const float4* xi = (const float4*)(in + (size_t)r * DIM);
    float4* xo = (float4*)(out + (size_t)r * DIM);
    int t = threadIdx.x;
    float4 v = xi[t];
    float s = v.x * v.x + v.y * v.y + v.z * v.z + v.w * v.w;
    __shared__ float sh[128];
    sh[t] = s; __syncthreads();
    for (int o = 64; o > 0; o >>= 1) { if (t < o) sh[t] += sh[t + o]; __syncthreads(); }
    float inv = rsqrtf(sh[0] + 1e-12f);
    xo[t] = make_float4(v.x * inv, v.y * inv, v.z * inv, v.w * inv);
}

// first-occurrence argmax over K=4096 (dist is fp32-accurate now)
__global__ void k_argmax(const float* __restrict__ dist) {
    int n = blockIdx.x;
    const float* row = dist + (size_t)n * KC;
    float best = -3.4e38f; int bi = KC;
    for (int j = threadIdx.x; j < KC; j += 256) {
        float v = row[j];
        if (v > best || (v == best && j < bi)) { best = v; bi = j; }
    }
    __shared__ float sv[256];
    __shared__ int   si[256];
    sv[threadIdx.x] = best; si[threadIdx.x] = bi; __syncthreads();
    for (int o = 128; o > 0; o >>= 1) {
        if (threadIdx.x < o) {
            float v2 = sv[threadIdx.x + o]; int i2 = si[threadIdx.x + o];
            if (v2 > sv[threadIdx.x] || (v2 == sv[threadIdx.x] && i2 < si[threadIdx.x])) {
                sv[threadIdx.x] = v2; si[threadIdx.x] = i2;
            }
        }
        __syncthreads();
    }
    if (threadIdx.x == 0) g_ind[n] = si[0];
}

__device__ __forceinline__ double blockReduceD(double v, double* sh) {
    int t = threadIdx.x;
    sh[t] = v; __syncthreads();
    for (int o = blockDim.x / 2; o > 0; o >>= 1) {
        if (t < o) sh[t] += sh[t + o];
        __syncthreads();
    }
    return sh[0];
}

__global__ void k_gather_commit() {
    int n = blockIdx.x;
    int idx = g_ind[n];
    const float4* e = (const float4*)(g_en + (size_t)idx * DIM);
    const float4* h = (const float4*)(g_h + (size_t)n * DIM);
    float4* q = (float4*)(g_q + (size_t)n * DIM);
    int t = threadIdx.x;
    float4 ev = e[t], hv = h[t];
    q[t] = ev;
    float dx = ev.x - hv.x, dy = ev.y - hv.y, dz = ev.z - hv.z, dw = ev.w - hv.w;
    double s = (double)dx * dx + (double)dy * dy + (double)dz * dz + (double)dw * dw;
    __shared__ double sh[128];
    double tot = blockReduceD(s, sh);
    if (t == 0) atomicAdd(&g_acc[0], tot);
}

__global__ void k_nodeloss() {
    const int tot = NNODE * DIM;
    double s = 0.0;
    for (int i = blockIdx.x * blockDim.x + threadIdx.x; i < tot; i += gridDim.x * blockDim.x) {
        float d = g_h[i] - g_qn[i];
        s += (double)d * d;
    }
    __shared__ double sh[256];
    double b = blockReduceD(s, sh);
    if (threadIdx.x == 0) atomicAdd(&g_acc[1], b);
}

__global__ void k_cnt_inc(const int* __restrict__ src, const int* __restrict__ dst) {
    int e = blockIdx.x * blockDim.x + threadIdx.x;
    if (e < NEDGE) atomicAdd(&g_cnt[(size_t)dst[e] * NNODE + src[e]], 1);
}

__global__ void k_edge_sum(const int* __restrict__ src, const int* __restrict__ dst) {
    double sx = 0.0, sc = 0.0;
    for (int e = blockIdx.x * blockDim.x + threadIdx.x; e < NEDGE; e += gridDim.x * blockDim.x) {
        size_t idx = (size_t)dst[e] * NNODE + src[e];
        sx += (double)g_adjq[idx];
        sc += (double)g_cnt[idx];
    }
    __shared__ double sh[256];
    double bx = blockReduceD(sx, sh);
    if (threadIdx.x == 0) atomicAdd(&g_acc[4], bx);
    __syncthreads();
    double bc = blockReduceD(sc, sh);
    if (threadIdx.x == 0) atomicAdd(&g_acc[5], bc);
}

__global__ void k_cnt_clear(const int* __restrict__ src, const int* __restrict__ dst) {
    int e = blockIdx.x * blockDim.x + threadIdx.x;
    if (e < NEDGE) g_cnt[(size_t)dst[e] * NNODE + src[e]] = 0;
}

__global__ void k_final(float* __restrict__ loss) {
    double nd = (double)NNODE * DIM;
    double commit = 0.25 * g_acc[0] / nd;
    double nodeL  = g_acc[1] / nd;
    double mn = (double)g_min, mx = (double)g_max;
    double inv = 1.0 / (mx - mn);
    double NN = (double)NNODE * (double)NNODE;
    double Sa2 = inv * inv * (g_acc[3] - 2.0 * mn * g_acc[2] + NN * mn * mn);
    double Sea = inv * (g_acc[4] - (double)NEDGE * mn);
    double tot = Sa2 - 2.0 * Sea + g_acc[5];
    double edgeL = sqrt(tot / NN);
    *loss = (float)(nodeL + edgeL + commit);
}

// ---------------- launch ----------------
extern "C" void kernel_launch(void* const* d_in, const int* in_sizes, int n_in,
                              void* d_out, int out_size) {
    (void)in_sizes; (void)n_in; (void)out_size;
    const float* feats = (const float*)d_in[0];
    const float* W1  = (const float*)d_in[1];
    const float* b1  = (const float*)d_in[2];
    const float* W2  = (const float*)d_in[3];
    const float* b2  = (const float*)d_in[4];
    const float* Wd1 = (const float*)d_in[5];
    const float* bd1 = (const float*)d_in[6];
    const float* Wd2 = (const float*)d_in[7];
    const float* bd2 = (const float*)d_in[8];
    const float* Wl  = (const float*)d_in[9];
    const float* bl  = (const float*)d_in[10];
    const float* cb  = (const float*)d_in[11];
    const int* src   = (const int*)d_in[12];
    const int* dst   = (const int*)d_in[13];

    float* out  = (float*)d_out;
    float* loss = out + (size_t)NNODE * NOUT;
    float* dist = loss + 1;

    float *p_h, *p_agg, *p_hn, *p_en, *p_q, *p_xe, *p_qn, *p_h2, *p_adjq;
    cudaGetSymbolAddress((void**)&p_h,    g_h);
    cudaGetSymbolAddress((void**)&p_agg,  g_agg);
    cudaGetSymbolAddress((void**)&p_hn,   g_hn);
    cudaGetSymbolAddress((void**)&p_en,   g_en);
    cudaGetSymbolAddress((void**)&p_q,    g_q);
    cudaGetSymbolAddress((void**)&p_xe,   g_xe);
    cudaGetSymbolAddress((void**)&p_qn,   g_qn);
    cudaGetSymbolAddress((void**)&p_h2,   g_h2);
    cudaGetSymbolAddress((void**)&p_adjq, g_adjq);

    #define TGRID(M, N) dim3(((N) + 127) / 128, ((M) + 127) / 128)

    k_init<<<1, 32>>>();
    k_zero_deg<<<(NNODE + 255) / 256, 256>>>();
    k_deg<<<(NEDGE + 255) / 256, 256>>>(src, dst);
    k_rsqrt_deg<<<(NNODE + 255) / 256, 256>>>();
    k_scan<<<1, 1024>>>();
    k_fill<<<(NEDGE + 255) / 256, 256>>>(src, dst);

    // GraphConv 1 (split precision: feeds dist/out paths)
    k_aggregate<<<NNODE, 128>>>(feats, p_agg);
    tgemm<false, true, true, false, true><<<TGRID(NNODE, DIM), 256>>>(
        p_agg, W1, b1, p_h, NNODE, DIM, DIM);

    // VQ (dist is a direct output: split precision)
    k_l2norm<<<KC, 128>>>(cb, p_en);
    k_l2norm<<<NNODE, 128>>>(p_h, p_hn);
    tgemm<true, false, false, false, true><<<TGRID(NNODE, KC), 256>>>(
        p_hn, p_en, nullptr, dist, NNODE, KC, DIM);
    k_argmax<<<NNODE, 256>>>(dist);
    k_gather_commit<<<NNODE, 128>>>();

    // decoders: xe feeds out path (split); qn is loss-only (plain tf32)
    tgemm<false, false, true, false, true><<<TGRID(NNODE, DIM), 256>>>(
        p_q, Wd1, bd1, p_xe, NNODE, DIM, DIM);
    tgemm<false, false, true, false, false><<<TGRID(NNODE, DIM), 256>>>(
        p_q, Wd2, bd2, p_qn, NNODE, DIM, DIM);
    k_nodeloss<<<512, 256>>>();

    // adjacency reconstruction (loss-only: plain tf32, stats fused)
    tgemm<true, false, false, true, false><<<TGRID(NNODE, NNODE), 256>>>(
        p_xe, p_xe, nullptr, p_adjq, NNODE, NNODE, DIM);
    k_cnt_inc<<<(NEDGE + 255) / 256, 256>>>(src, dst);
    k_edge_sum<<<256, 256>>>(src, dst);
    k_cnt_clear<<<(NEDGE + 255) / 256, 256>>>(src, dst);

    // GraphConv 2 + head (out path: split; head in exact fp32)
    k_aggregate<<<NNODE, 128>>>(p_xe, p_agg);
    tgemm<false, true, true, false, true><<<TGRID(NNODE, DIM), 256>>>(
        p_agg, W2, b2, p_h2, NNODE, DIM, DIM);
    gemm_head<<<dim3(1, (NNODE + 63) / 64), 256>>>(p_h2, Wl, bl, out, NNODE, NOUT, DIM);

    k_final<<<1, 1>>>(loss);
    #undef TGRID
}

// round 4
// speedup vs baseline: 2.3098x; 1.0853x over previous
#include <cuda_runtime.h>
#include <math.h>
#include <float.h>

// ---------------- problem constants ----------------
#define NNODE 6000
#define NEDGE 192000
#define DIM   512
#define NOUT  40
#define KC    4096

// ---------------- device scratch ----------------
__device__ float g_h  [NNODE * DIM];
__device__ float g_agg[NNODE * DIM];
__device__ float g_hn [NNODE * DIM];
__device__ float g_en [KC * DIM];
__device__ float g_q  [NNODE * DIM];
__device__ float g_xe [NNODE * DIM];
__device__ float g_qn [NNODE * DIM];
__device__ float g_h2 [NNODE * DIM];
__device__ int   g_dego[NNODE];
__device__ int   g_degi[NNODE];
__device__ float g_rso [NNODE];
__device__ float g_rsi [NNODE];
__device__ int   g_ind [NNODE];
__device__ int   g_rowptr[NNODE + 1];
__device__ int   g_cur [NNODE];
__device__ int   g_srcs[NEDGE];
__device__ double g_acc[8];   // 0:commit 1:node 2:sum_x 3:sum_x2 4:edge_sum_x 5:dupcount
__device__ float g_min, g_max;

// ---------------- helpers ----------------
__device__ __forceinline__ void atomicMinF(float* a, float v) {
    int old = __float_as_int(*a);
    while (v < __int_as_float(old)) {
        int assumed = old;
        old = atomicCAS((int*)a, assumed, __float_as_int(v));
        if (old == assumed) break;
    }
}
__device__ __forceinline__ void atomicMaxF(float* a, float v) {
    int old = __float_as_int(*a);
    while (v > __int_as_float(old)) {
        int assumed = old;
        old = atomicCAS((int*)a, assumed, __float_as_int(v));
        if (old == assumed) break;
    }
}
__device__ __forceinline__ unsigned f2tf(float f) {
    unsigned u;
    asm("cvt.rna.tf32.f32 %0, %1;" : "=r"(u) : "f"(f));
    return u;
}
__device__ __forceinline__ void mma_tf32(float c[4], unsigned a0, unsigned a1,
                                         unsigned a2, unsigned a3,
                                         unsigned b0, unsigned b1) {
    asm volatile(
        "mma.sync.aligned.m16n8k8.row.col.f32.tf32.tf32.f32 "
        "{%0,%1,%2,%3}, {%4,%5,%6,%7}, {%8,%9}, {%0,%1,%2,%3};\n"
        : "+f"(c[0]), "+f"(c[1]), "+f"(c[2]), "+f"(c[3])
        : "r"(a0), "r"(a1), "r"(a2), "r"(a3), "r"(b0), "r"(b1));
}

// ================= TF32 tensor-core GEMM =================
// C[M,N] = A[M,K] @ op(B) (+bias) (relu) (stats) (optional store)
// TRANSB=true: B is [N,K] row-major (C = A @ B^T). false: B is [K,N] row-major.
// SPLIT: 3xTF32 (fp32-grade), single smem stage. Plain: 2-stage double buffer.
// Tiles: BM=BN=128, BK=16, 256 threads = 8 warps (2m x 4n), warp tile 64x32.
template <bool TRANSB, bool RELU, bool BIAS, bool STATS, bool SPLIT, bool STORE>
__global__ void __launch_bounds__(256) tgemm(
    const float* __restrict__ A, const float* __restrict__ B,
    const float* __restrict__ bias, float* __restrict__ C,
    int M, int N, int K)
{
    constexpr int AW = 128 * 20;
    constexpr int BW = TRANSB ? 128 * 20 : 16 * 132;
    constexpr int NBUF = SPLIT ? 2 : 1;
    constexpr int STAGES = SPLIT ? 1 : 2;
    constexpr int STRIDE = NBUF * (AW + BW);
    constexpr int WORDS = STAGES * STRIDE;
    __shared__ __align__(16) unsigned sm[WORDS < 768 ? 768 : WORDS];

    const int tid  = threadIdx.x;
    const int warp = tid >> 5, lane = tid & 31;
    const int g    = lane >> 2, c4 = lane & 3;
    const int wm   = (warp & 1) * 64, wn = (warp >> 1) * 32;
    const int bm   = blockIdx.y * 128, bn = blockIdx.x * 128;

    float acc[4][4][4];
#pragma unroll
    for (int i = 0; i < 4; i++)
#pragma unroll
        for (int j = 0; j < 4; j++)
#pragma unroll
            for (int r = 0; r < 4; r++) acc[i][j][r] = 0.f;

    float4 arv[2], brv[2];

    auto ldg_stage = [&](int k0) {
#pragma unroll
        for (int p = 0; p < 2; p++) {
            int idx = p * 256 + tid;
            int r = idx >> 2, kc = (idx & 3) * 4;
            int gr = bm + r;
            arv[p] = (gr < M) ? *(const float4*)(A + (size_t)gr * K + k0 + kc)
                              : make_float4(0.f, 0.f, 0.f, 0.f);
        }
        if (TRANSB) {
#pragma unroll
            for (int p = 0; p < 2; p++) {
                int idx = p * 256 + tid;
                int r = idx >> 2, kc = (idx & 3) * 4;
                int gn = bn + r;
                brv[p] = (gn < N) ? *(const float4*)(B + (size_t)gn * K + k0 + kc)
                                  : make_float4(0.f, 0.f, 0.f, 0.f);
            }
        } else {
#pragma unroll
            for (int p = 0; p < 2; p++) {
                int idx = p * 256 + tid;
                int kr = idx >> 5, nc = (idx & 31) * 4;
                int col = bn + nc;
                const float* bp = B + (size_t)(k0 + kr) * N;
                float4 v = make_float4(0.f, 0.f, 0.f, 0.f);
                if (col + 3 < N) v = *(const float4*)(bp + col);
                else {
                    if (col + 0 < N) v.x = bp[col + 0];
                    if (col + 1 < N) v.y = bp[col + 1];
                    if (col + 2 < N) v.z = bp[col + 2];
                }
                brv[p] = v;
            }
        }
    };

    auto cvt_store = [&](const float4& v, unsigned* hi, unsigned* lo, int off) {
        unsigned hx = f2tf(v.x), hy = f2tf(v.y), hz = f2tf(v.z), hw = f2tf(v.w);
        *(uint4*)(hi + off) = make_uint4(hx, hy, hz, hw);
        if (SPLIT) {
            unsigned lx = f2tf(v.x - __uint_as_float(hx));
            unsigned ly = f2tf(v.y - __uint_as_float(hy));
            unsigned lz = f2tf(v.z - __uint_as_float(hz));
            unsigned lw = f2tf(v.w - __uint_as_float(hw));
            *(uint4*)(lo + off) = make_uint4(lx, ly, lz, lw);
        }
    };

    auto sts_stage = [&](int s) {
        unsigned* Ah = sm + s * STRIDE;
        unsigned* Al = Ah + AW;
        unsigned* Bh = sm + s * STRIDE + NBUF * AW;
        unsigned* Bl = Bh + BW;
#pragma unroll
        for (int p = 0; p < 2; p++) {
            int idx = p * 256 + tid;
            int r = idx >> 2, kc = (idx & 3) * 4;
            cvt_store(arv[p], Ah, Al, r * 20 + kc);
        }
#pragma unroll
        for (int p = 0; p < 2; p++) {
            int idx = p * 256 + tid;
            if (TRANSB) {
                int r = idx >> 2, kc = (idx & 3) * 4;
                cvt_store(brv[p], Bh, Bl, r * 20 + kc);
            } else {
                int kr = idx >> 5, nc = (idx & 31) * 4;
                cvt_store(brv[p], Bh, Bl, kr * 132 + nc);
            }
        }
    };

    auto compute = [&](int s) {
        unsigned* Ah = sm + s * STRIDE;
        unsigned* Al = Ah + AW;
        unsigned* Bh = sm + s * STRIDE + NBUF * AW;
        unsigned* Bl = Bh + BW;
#pragma unroll
        for (int kk = 0; kk < 16; kk += 8) {
            unsigned ah[4][4], al[4][4], bh[4][2], bl[4][2];
#pragma unroll
            for (int mt = 0; mt < 4; mt++) {
                int row = wm + mt * 16 + g;
                ah[mt][0] = Ah[row * 20 + kk + c4];
                ah[mt][1] = Ah[(row + 8) * 20 + kk + c4];
                ah[mt][2] = Ah[row * 20 + kk + c4 + 4];
                ah[mt][3] = Ah[(row + 8) * 20 + kk + c4 + 4];
                if (SPLIT) {
                    al[mt][0] = Al[row * 20 + kk + c4];
                    al[mt][1] = Al[(row + 8) * 20 + kk + c4];
                    al[mt][2] = Al[row * 20 + kk + c4 + 4];
                    al[mt][3] = Al[(row + 8) * 20 + kk + c4 + 4];
                }
            }
#pragma unroll
            for (int nt = 0; nt < 4; nt++) {
                int col = wn + nt * 8 + g;
                if (TRANSB) {
                    bh[nt][0] = Bh[col * 20 + kk + c4];
                    bh[nt][1] = Bh[col * 20 + kk + c4 + 4];
                    if (SPLIT) {
                        bl[nt][0] = Bl[col * 20 + kk + c4];
                        bl[nt][1] = Bl[col * 20 + kk + c4 + 4];
                    }
                } else {
                    bh[nt][0] = Bh[(kk + c4) * 132 + col];
                    bh[nt][1] = Bh[(kk + c4 + 4) * 132 + col];
                    if (SPLIT) {
                        bl[nt][0] = Bl[(kk + c4) * 132 + col];
                        bl[nt][1] = Bl[(kk + c4 + 4) * 132 + col];
                    }
                }
            }
#pragma unroll
            for (int mt = 0; mt < 4; mt++)
#pragma unroll
                for (int nt = 0; nt < 4; nt++) {
                    mma_tf32(acc[mt][nt], ah[mt][0], ah[mt][1], ah[mt][2], ah[mt][3],
                             bh[nt][0], bh[nt][1]);
                    if (SPLIT) {
                        mma_tf32(acc[mt][nt], ah[mt][0], ah[mt][1], ah[mt][2], ah[mt][3],
                                 bl[nt][0], bl[nt][1]);
                        mma_tf32(acc[mt][nt], al[mt][0], al[mt][1], al[mt][2], al[mt][3],
                                 bh[nt][0], bh[nt][1]);
                    }
                }
        }
    };

    const int KT = K / 16;
    if (STAGES == 2) {
        ldg_stage(0);
        sts_stage(0);
        __syncthreads();
        for (int kt = 0; kt < KT; ++kt) {
            if (kt + 1 < KT) ldg_stage((kt + 1) * 16);
            compute(kt & 1);
            if (kt + 1 < KT) {
                sts_stage((kt + 1) & 1);
                __syncthreads();
            }
        }
    } else {
        ldg_stage(0);
        for (int kt = 0; kt < KT; ++kt) {
            sts_stage(0);
            __syncthreads();
            if (kt + 1 < KT) ldg_stage((kt + 1) * 16);
            compute(0);
            __syncthreads();
        }
    }

    // ---- epilogue (scalar stores: C may be only 4-byte aligned) ----
    float  lmn = FLT_MAX, lmx = -FLT_MAX;
    double ls = 0.0, ls2 = 0.0;
#pragma unroll
    for (int mt = 0; mt < 4; mt++) {
#pragma unroll
        for (int nt = 0; nt < 4; nt++) {
            int col = bn + wn + nt * 8 + 2 * c4;
            bool ok0 = col < N, ok1 = col + 1 < N;
            float bias0 = 0.f, bias1 = 0.f;
            if (BIAS) { if (ok0) bias0 = bias[col]; if (ok1) bias1 = bias[col + 1]; }
#pragma unroll
            for (int half = 0; half < 2; half++) {
                int rr = bm + wm + mt * 16 + g + 8 * half;
                if (rr >= M) continue;
                float v0 = acc[mt][nt][half * 2 + 0] + bias0;
                float v1 = acc[mt][nt][half * 2 + 1] + bias1;
                if (RELU) { v0 = fmaxf(v0, 0.f); v1 = fmaxf(v1, 0.f); }
                if (STORE) {
                    if (ok0) C[(size_t)rr * N + col] = v0;
                    if (ok1) C[(size_t)rr * N + col + 1] = v1;
                }
                if (STATS) {
                    if (ok0) {
                        lmn = fminf(lmn, v0); lmx = fmaxf(lmx, v0);
                        ls += (double)v0; ls2 += (double)v0 * v0;
                    }
                    if (ok1) {
                        lmn = fminf(lmn, v1); lmx = fmaxf(lmx, v1);
                        ls += (double)v1; ls2 += (double)v1 * v1;
                    }
                }
            }
        }
    }

    if (STATS) {
        __syncthreads();
        double* rb = (double*)sm;
        rb[tid] = ls; __syncthreads();
        for (int o = 128; o > 0; o >>= 1) { if (tid < o) rb[tid] += rb[tid + o]; __syncthreads(); }
        if (tid == 0) atomicAdd(&g_acc[2], rb[0]);
        __syncthreads();
        rb[tid] = ls2; __syncthreads();
        for (int o = 128; o > 0; o >>= 1) { if (tid < o) rb[tid] += rb[tid + o]; __syncthreads(); }
        if (tid == 0) atomicAdd(&g_acc[3], rb[0]);
        __syncthreads();
        float* fb = (float*)sm;
        fb[tid] = lmn; __syncthreads();
        for (int o = 128; o > 0; o >>= 1) { if (tid < o) fb[tid] = fminf(fb[tid], fb[tid + o]); __syncthreads(); }
        if (tid == 0) atomicMinF(&g_min, fb[0]);
        __syncthreads();
        fb[tid] = lmx; __syncthreads();
        for (int o = 128; o > 0; o >>= 1) { if (tid < o) fb[tid] = fmaxf(fb[tid], fb[tid + o]); __syncthreads(); }
        if (tid == 0) atomicMaxF(&g_max, fb[0]);
    }
}

// ================= fp32 SIMT GEMM (head only, N=40) =================
__global__ void gemm_head(const float* __restrict__ A, const float* __restrict__ B,
                          const float* __restrict__ bias, float* __restrict__ C,
                          int M, int N, int K)
{
    __shared__ __align__(16) float As[16][64];
    __shared__ __align__(16) float Bs[16][64];
    const int tid = threadIdx.x;
    const int bm = blockIdx.y * 64, bn = blockIdx.x * 64;
    const int ty = tid >> 4, tx = tid & 15;
    float acc[4][4];
#pragma unroll
    for (int i = 0; i < 4; i++)
#pragma unroll
        for (int j = 0; j < 4; j++) acc[i][j] = 0.f;

    const int ar = tid >> 2, ac = (tid & 3) * 4;
    const int gr = bm + ar;
    for (int k0 = 0; k0 < K; k0 += 16) {
        float4 av = make_float4(0.f, 0.f, 0.f, 0.f);
        if (gr < M) av = *(const float4*)(A + (size_t)gr * K + k0 + ac);
        As[ac + 0][ar] = av.x; As[ac + 1][ar] = av.y;
        As[ac + 2][ar] = av.z; As[ac + 3][ar] = av.w;

        const int br = tid >> 4, bc = (tid & 15) * 4;
        const int gn = bn + bc;
        float4 bv = make_float4(0.f, 0.f, 0.f, 0.f);
        const float* bp = B + (size_t)(k0 + br) * N;
        if (gn + 3 < N) bv = *(const float4*)(bp + gn);
        else {
            if (gn + 0 < N) bv.x = bp[gn + 0];
            if (gn + 1 < N) bv.y = bp[gn + 1];
            if (gn + 2 < N) bv.z = bp[gn + 2];
        }
        Bs[br][bc + 0] = bv.x; Bs[br][bc + 1] = bv.y;
        Bs[br][bc + 2] = bv.z; Bs[br][bc + 3] = bv.w;
        __syncthreads();
#pragma unroll
        for (int k = 0; k < 16; k++) {
            float a[4], b[4];
            *(float4*)a = *(const float4*)&As[k][ty * 4];
            *(float4*)b = *(const float4*)&Bs[k][tx * 4];
#pragma unroll
            for (int i = 0; i < 4; i++)
#pragma unroll
                for (int j = 0; j < 4; j++) acc[i][j] = fmaf(a[i], b[j], acc[i][j]);
        }
        __syncthreads();
    }
#pragma unroll
    for (int i = 0; i < 4; i++) {
        int gm = bm + ty * 4 + i;
        if (gm >= M) continue;
#pragma unroll
        for (int j = 0; j < 4; j++) {
            int gn = bn + tx * 4 + j;
            if (gn >= N) continue;
            C[(size_t)gm * N + gn] = acc[i][j] + bias[gn];
        }
    }
}

// ---------------- aux kernels ----------------
__global__ void k_init() {
    int t = threadIdx.x;
    if (t < 8) g_acc[t] = 0.0;
    if (t == 8) g_min = __int_as_float(0x7f800000);
    if (t == 9) g_max = __int_as_float(0xff800000);
}

__global__ void k_zero_deg() {
    int i = blockIdx.x * blockDim.x + threadIdx.x;
    if (i < NNODE) { g_dego[i] = 0; g_degi[i] = 0; }
}

__global__ void k_deg(const int* __restrict__ src, const int* __restrict__ dst) {
    int e = blockIdx.x * blockDim.x + threadIdx.x;
    if (e < NEDGE) {
        atomicAdd(&g_dego[src[e]], 1);
        atomicAdd(&g_degi[dst[e]], 1);
    }
}

__global__ void k_rsqrt_deg() {
    int i = blockIdx.x * blockDim.x + threadIdx.x;
    if (i < NNODE) {
        g_rso[i] = rsqrtf(fmaxf((float)g_dego[i], 1.f));
        g_rsi[i] = rsqrtf(fmaxf((float)g_degi[i], 1.f));
    }
}

// single-block scan over in-degrees -> CSR row pointers
__global__ void k_scan() {
    __shared__ int part[1024];
    int t = threadIdx.x;
    int base = t * 6;
    int loc[6]; int s = 0;
#pragma unroll
    for (int i = 0; i < 6; i++) {
        int idx = base + i; loc[i] = s;
        if (idx < NNODE) s += g_degi[idx];
    }
    part[t] = s; __syncthreads();
    for (int off = 1; off < 1024; off <<= 1) {
        int v = (t >= off) ? part[t - off] : 0;
        __syncthreads();
        part[t] += v;
        __syncthreads();
    }
    int pre = (t > 0) ? part[t - 1] : 0;
#pragma unroll
    for (int i = 0; i < 6; i++) {
        int idx = base + i;
        if (idx < NNODE) { g_rowptr[idx] = pre + loc[i]; g_cur[idx] = pre + loc[i]; }
    }
    if (t == 0) g_rowptr[NNODE] = NEDGE;
}

__global__ void k_fill(const int* __restrict__ src, const int* __restrict__ dst) {
    int e = blockIdx.x * blockDim.x + threadIdx.x;
    if (e < NEDGE) {
        int p = atomicAdd(&g_cur[dst[e]], 1);
        g_srcs[p] = src[e];
    }
}

// CSR gather-aggregate: out[n] = rsi[n] * sum_{e in in(n)} x[src(e)] * rso[src(e)]
__global__ void k_aggregate(const float* __restrict__ x, float* __restrict__ o) {
    int n = blockIdx.x, t = threadIdx.x;   // 128 threads, DIM/4 = 128
    int beg = g_rowptr[n], end = g_rowptr[n + 1];
    float ax = 0.f, ay = 0.f, az = 0.f, aw = 0.f;
    for (int e = beg; e < end; e++) {
        int s = g_srcs[e];
        float rs = g_rso[s];
        float4 v = ((const float4*)x)[(size_t)s * 128 + t];
        ax = fmaf(v.x, rs, ax); ay = fmaf(v.y, rs, ay);
        az = fmaf(v.z, rs, az); aw = fmaf(v.w, rs, aw);
    }
    float ri = g_rsi[n];
    ((float4*)o)[(size_t)n * 128 + t] = make_float4(ax * ri, ay * ri, az * ri, aw * ri);
}

// row-wise L2 normalize (D=512)
__global__ void k_l2norm(const float* __restrict__ in, float* __restrict__ out) {
    int r = blockIdx.x;
    const float4* xi = (const float4*)(in + (size_t)r * DIM);
    float4* xo = (float4*)(out + (size_t)r * DIM);
    int t = threadIdx.x;
    float4 v = xi[t];
    float s = v.x * v.x + v.y * v.y + v.z * v.z + v.w * v.w;
    __shared__ float sh[128];
    sh[t] = s; __syncthreads();
    for (int o = 64; o > 0; o >>= 1) { if (t < o) sh[t] += sh[t + o]; __syncthreads(); }
    float inv = rsqrtf(sh[0] + 1e-12f);
    xo[t] = make_float4(v.x * inv, v.y * inv, v.z * inv, v.w * inv);
}

// argmax over tf32 dist with exact fp32 rescue among near-max candidates
__global__ void k_argmax(const float* __restrict__ dist, const float* __restrict__ hn,
                         const float* __restrict__ en) {
    int n = blockIdx.x, t = threadIdx.x;   // 256 threads
    const float* row = dist + (size_t)n * KC;
    float m = -3.4e38f;
    for (int j = t; j < KC; j += 256) m = fmaxf(m, row[j]);
    __shared__ float smax[256];
    smax[t] = m; __syncthreads();
    for (int o = 128; o > 0; o >>= 1) { if (t < o) smax[t] = fmaxf(smax[t], smax[t + o]); __syncthreads(); }
    float thr = smax[0] - 2.5e-4f;

    const float4* h4 = (const float4*)(hn + (size_t)n * DIM);
    float bv = -3.4e38f; int bj = KC;
    for (int j = t; j < KC; j += 256) {
        if (row[j] >= thr) {
            const float4* e4 = (const float4*)(en + (size_t)j * DIM);
            float s0 = 0.f, s1 = 0.f, s2 = 0.f, s3 = 0.f;
            for (int k = 0; k < 128; k++) {
                float4 a = h4[k], b = e4[k];
                s0 = fmaf(a.x, b.x, s0); s1 = fmaf(a.y, b.y, s1);
                s2 = fmaf(a.z, b.z, s2); s3 = fmaf(a.w, b.w, s3);
            }
            float s = (s0 + s1) + (s2 + s3);
            if (s > bv || (s == bv && j < bj)) { bv = s; bj = j; }
        }
    }
    __shared__ float sv[256];
    __shared__ int   si[256];
    sv[t] = bv; si[t] = bj; __syncthreads();
    for (int o = 128; o > 0; o >>= 1) {
        if (t < o) {
            float v2 = sv[t + o]; int i2 = si[t + o];
            if (v2 > sv[t] || (v2 == sv[t] && i2 < si[t])) { sv[t] = v2; si[t] = i2; }
        }
        __syncthreads();
    }
    if (t == 0) g_ind[n] = si[0];
}

__device__ __forceinline__ double blockReduceD(double v, double* sh) {
    int t = threadIdx.x;
    sh[t] = v; __syncthreads();
    for (int o = blockDim.x / 2; o > 0; o >>= 1) {
        if (t < o) sh[t] += sh[t + o];
        __syncthreads();
    }
    return sh[0];
}

__global__ void k_gather_commit() {
    int n = blockIdx.x;
    int idx = g_ind[n];
    const float4* e = (const float4*)(g_en + (size_t)idx * DIM);
    const float4* h = (const float4*)(g_h + (size_t)n * DIM);
    float4* q = (float4*)(g_q + (size_t)n * DIM);
    int t = threadIdx.x;
    float4 ev = e[t], hv = h[t];
    q[t] = ev;
    float dx = ev.x - hv.x, dy = ev.y - hv.y, dz = ev.z - hv.z, dw = ev.w - hv.w;
    double s = (double)dx * dx + (double)dy * dy + (double)dz * dz + (double)dw * dw;
    __shared__ double sh[128];
    double tot = blockReduceD(s, sh);
    if (t == 0) atomicAdd(&g_acc[0], tot);
}

__global__ void k_nodeloss() {
    const int tot = NNODE * DIM;
    double s = 0.0;
    for (int i = blockIdx.x * blockDim.x + threadIdx.x; i < tot; i += gridDim.x * blockDim.x) {
        float d = g_h[i] - g_qn[i];
        s += (double)d * d;
    }
    __shared__ double sh[256];
    double b = blockReduceD(s, sh);
    if (threadIdx.x == 0) atomicAdd(&g_acc[1], b);
}

// exact fp32 dot xe[dst[e]] . xe[src[e]] per edge (warp per edge), summed (with multiplicity)
__global__ void k_edge_dot(const int* __restrict__ src, const int* __restrict__ dst) {
    int gw = (blockIdx.x * blockDim.x + threadIdx.x) >> 5;
    int lane = threadIdx.x & 31;
    float s = 0.f;
    if (gw < NEDGE) {
        const float4* a = (const float4*)(g_xe + (size_t)dst[gw] * DIM);
        const float4* b = (const float4*)(g_xe + (size_t)src[gw] * DIM);
#pragma unroll
        for (int i = 0; i < 4; i++) {
            float4 x = a[lane + 32 * i], y = b[lane + 32 * i];
            s += x.x * y.x + x.y * y.y + x.z * y.z + x.w * y.w;
        }
    }
#pragma unroll
    for (int o = 16; o > 0; o >>= 1) s += __shfl_xor_sync(0xffffffffu, s, o);
    __shared__ double sh[8];
    if (lane == 0) sh[threadIdx.x >> 5] = (gw < NEDGE) ? (double)s : 0.0;
    __syncthreads();
    if (threadIdx.x == 0) {
        double tot = 0.0;
        for (int i = 0; i < 8; i++) tot += sh[i];
        atomicAdd(&g_acc[4], tot);
    }
}

// duplicate-edge multiplicity: sum over CSR rows of #{(i,j) : src_i == src_j} = sum_distinct c^2
__global__ void k_dup() {
    int n = blockIdx.x;
    int beg = g_rowptr[n], end = g_rowptr[n + 1];
    int L = end - beg;
    __shared__ int srow[1024];
    bool cached = (L <= 1024);
    if (cached)
        for (int i = threadIdx.x; i < L; i += blockDim.x) srow[i] = g_srcs[beg + i];
    __syncthreads();
    int cnt = 0;
    for (int i = 0; i < L; i++) {
        int si = cached ? srow[i] : g_srcs[beg + i];
        for (int j = threadIdx.x; j < L; j += blockDim.x) {
            int sj = cached ? srow[j] : g_srcs[beg + j];
            cnt += (si == sj);
        }
    }
    __shared__ int sc[128];
    sc[threadIdx.x] = cnt; __syncthreads();
    for (int o = 64; o > 0; o >>= 1) {
        if (threadIdx.x < o) sc[threadIdx.x] += sc[threadIdx.x + o];
        __syncthreads();
    }
    if (threadIdx.x == 0) atomicAdd(&g_acc[5], (double)sc[0]);
}

__global__ void k_final(float* __restrict__ loss) {
    double nd = (double)NNODE * DIM;
    double commit = 0.25 * g_acc[0] / nd;
    double nodeL  = g_acc[1] / nd;
    double mn = (double)g_min, mx = (double)g_max;
    double inv = 1.0 / (mx - mn);
    double NN = (double)NNODE * (double)NNODE;
    double Sa2 = inv * inv * (g_acc[3] - 2.0 * mn * g_acc[2] + NN * mn * mn);
    double Sea = inv * (g_acc[4] - (double)NEDGE * mn);
    double tot = Sa2 - 2.0 * Sea + g_acc[5];
    double edgeL = sqrt(tot / NN);
    *loss = (float)(nodeL + edgeL + commit);
}

// ---------------- launch ----------------
extern "C" void kernel_launch(void* const* d_in, const int* in_sizes, int n_in,
                              void* d_out, int out_size) {
    (void)in_sizes; (void)n_in; (void)out_size;
    const float* feats = (const float*)d_in[0];
    const float* W1  = (const float*)d_in[1];
    const float* b1  = (const float*)d_in[2];
    const float* W2  = (const float*)d_in[3];
    const float* b2  = (const float*)d_in[4];
    const float* Wd1 = (const float*)d_in[5];
    const float* bd1 = (const float*)d_in[6];
    const float* Wd2 = (const float*)d_in[7];
    const float* bd2 = (const float*)d_in[8];
    const float* Wl  = (const float*)d_in[9];
    const float* bl  = (const float*)d_in[10];
    const float* cb  = (const float*)d_in[11];
    const int* src   = (const int*)d_in[12];
    const int* dst   = (const int*)d_in[13];

    float* out  = (float*)d_out;
    float* loss = out + (size_t)NNODE * NOUT;
    float* dist = loss + 1;

    float *p_h, *p_agg, *p_hn, *p_en, *p_q, *p_xe, *p_qn, *p_h2;
    cudaGetSymbolAddress((void**)&p_h,   g_h);
    cudaGetSymbolAddress((void**)&p_agg, g_agg);
    cudaGetSymbolAddress((void**)&p_hn,  g_hn);
    cudaGetSymbolAddress((void**)&p_en,  g_en);
    cudaGetSymbolAddress((void**)&p_q,   g_q);
    cudaGetSymbolAddress((void**)&p_xe,  g_xe);
    cudaGetSymbolAddress((void**)&p_qn,  g_qn);
    cudaGetSymbolAddress((void**)&p_h2,  g_h2);

    #define TGRID(M, N) dim3(((N) + 127) / 128, ((M) + 127) / 128)

    k_init<<<1, 32>>>();
    k_zero_deg<<<(NNODE + 255) / 256, 256>>>();
    k_deg<<<(NEDGE + 255) / 256, 256>>>(src, dst);
    k_rsqrt_deg<<<(NNODE + 255) / 256, 256>>>();
    k_scan<<<1, 1024>>>();
    k_fill<<<(NEDGE + 255) / 256, 256>>>(src, dst);

    // GraphConv 1 (split precision: feeds dist/out paths)
    k_aggregate<<<NNODE, 128>>>(feats, p_agg);
    tgemm<false, true, true, false, true, true><<<TGRID(NNODE, DIM), 256>>>(
        p_agg, W1, b1, p_h, NNODE, DIM, DIM);

    // VQ: dist in plain tf32 (2-stage pipelined) + exact-fp32 argmax rescue
    k_l2norm<<<KC, 128>>>(cb, p_en);
    k_l2norm<<<NNODE, 128>>>(p_h, p_hn);
    tgemm<true, false, false, false, false, true><<<TGRID(NNODE, KC), 256>>>(
        p_hn, p_en, nullptr, dist, NNODE, KC, DIM);
    k_argmax<<<NNODE, 256>>>(dist, p_hn, p_en);
    k_gather_commit<<<NNODE, 128>>>();

    // decoders: xe feeds out path (split); qn is loss-only (plain tf32)
    tgemm<false, false, true, false, true, true><<<TGRID(NNODE, DIM), 256>>>(
        p_q, Wd1, bd1, p_xe, NNODE, DIM, DIM);
    tgemm<false, false, true, false, false, true><<<TGRID(NNODE, DIM), 256>>>(
        p_q, Wd2, bd2, p_qn, NNODE, DIM, DIM);
    k_nodeloss<<<512, 256>>>();

    // adjacency reconstruction: stats-only GEMM (no store), exact edge dots, dup counts
    tgemm<true, false, false, true, false, false><<<TGRID(NNODE, NNODE), 256>>>(
        p_xe, p_xe, nullptr, nullptr, NNODE, NNODE, DIM);
    k_edge_dot<<<(NEDGE * 32 + 255) / 256, 256>>>(src, dst);
    k_dup<<<NNODE, 128>>>();

    // GraphConv 2 + head (out path: split; head in exact fp32)
    k_aggregate<<<NNODE, 128>>>(p_xe, p_agg);
    tgemm<false, true, true, false, true, true><<<TGRID(NNODE, DIM), 256>>>(
        p_agg, W2, b2, p_h2, NNODE, DIM, DIM);
    gemm_head<<<dim3(1, (NNODE + 63) / 64), 256>>>(p_h2, Wl, bl, out, NNODE, NOUT, DIM);

    k_final<<<1, 1>>>(loss);
    #undef TGRID
}

// round 5
// speedup vs baseline: 2.6886x; 1.1640x over previous
#include <cuda_runtime.h>
#include <math.h>
#include <float.h>

// ---------------- problem constants ----------------
#define NNODE 6000
#define NEDGE 192000
#define DIM   512
#define NOUT  40
#define KC    4096

// ---------------- device scratch ----------------
__device__ float g_h  [NNODE * DIM];
__device__ float g_agg[NNODE * DIM];
__device__ float g_hn [NNODE * DIM];
__device__ float g_en [KC * DIM];
__device__ float g_q  [NNODE * DIM];
__device__ float g_xe [NNODE * DIM];
__device__ float g_h2 [NNODE * DIM];
__device__ int   g_dego[NNODE];
__device__ int   g_degi[NNODE];
__device__ float g_rso [NNODE];
__device__ float g_rsi [NNODE];
__device__ int   g_ind [NNODE];
__device__ int   g_rowptr[NNODE + 1];
__device__ int   g_cur [NNODE];
__device__ int   g_srcs[NEDGE];
__device__ double g_acc[8];   // 0:commit 1:node 2:sum_x 3:sum_x2 4:edge_sum_x 5:dupcount
__device__ float g_min, g_max;

// ---------------- helpers ----------------
__device__ __forceinline__ void atomicMinF(float* a, float v) {
    int old = __float_as_int(*a);
    while (v < __int_as_float(old)) {
        int assumed = old;
        old = atomicCAS((int*)a, assumed, __float_as_int(v));
        if (old == assumed) break;
    }
}
__device__ __forceinline__ void atomicMaxF(float* a, float v) {
    int old = __float_as_int(*a);
    while (v > __int_as_float(old)) {
        int assumed = old;
        old = atomicCAS((int*)a, assumed, __float_as_int(v));
        if (old == assumed) break;
    }
}
__device__ __forceinline__ unsigned f2tf(float f) {
    unsigned u;
    asm("cvt.rna.tf32.f32 %0, %1;" : "=r"(u) : "f"(f));
    return u;
}
__device__ __forceinline__ void mma_tf32(float c[4], unsigned a0, unsigned a1,
                                         unsigned a2, unsigned a3,
                                         unsigned b0, unsigned b1) {
    asm volatile(
        "mma.sync.aligned.m16n8k8.row.col.f32.tf32.tf32.f32 "
        "{%0,%1,%2,%3}, {%4,%5,%6,%7}, {%8,%9}, {%0,%1,%2,%3};\n"
        : "+f"(c[0]), "+f"(c[1]), "+f"(c[2]), "+f"(c[3])
        : "r"(a0), "r"(a1), "r"(a2), "r"(a3), "r"(b0), "r"(b1));
}

// ================= TF32 tensor-core GEMM =================
// C[M,N] = A[M,K] @ op(B) (+bias) (relu) (stats) (opt store) (opt sym) (opt nodeloss)
// TRANSB=true: B is [N,K] row-major (C = A @ B^T). false: B is [K,N] row-major.
// SPLIT: 3xTF32 (fp32-grade), single smem stage. Plain: 2-stage double buffer.
// SYM: only computes tiles with bx>=by (caller guarantees symmetric C; stats x2 off-diag).
// NLOSS: accumulate sum((g_h - C)^2) instead of storing.
// Tiles: BM=BN=128, BK=16, 256 threads = 8 warps (2m x 4n), warp tile 64x32.
template <bool TRANSB, bool RELU, bool BIAS, bool STATS, bool SPLIT, bool STORE,
          bool SYM, bool NLOSS>
__global__ void __launch_bounds__(256) tgemm(
    const float* __restrict__ A, const float* __restrict__ B,
    const float* __restrict__ bias, float* __restrict__ C,
    int M, int N, int K)
{
    if (SYM && blockIdx.x < blockIdx.y) return;

    constexpr int AW = 128 * 20;
    constexpr int BW = TRANSB ? 128 * 20 : 16 * 132;
    constexpr int NBUF = SPLIT ? 2 : 1;
    constexpr int STAGES = SPLIT ? 1 : 2;
    constexpr int STRIDE = NBUF * (AW + BW);
    constexpr int WORDS = STAGES * STRIDE;
    __shared__ __align__(16) unsigned sm[WORDS < 768 ? 768 : WORDS];

    const int tid  = threadIdx.x;
    const int warp = tid >> 5, lane = tid & 31;
    const int g    = lane >> 2, c4 = lane & 3;
    const int wm   = (warp & 1) * 64, wn = (warp >> 1) * 32;
    const int bm   = blockIdx.y * 128, bn = blockIdx.x * 128;

    float acc[4][4][4];
#pragma unroll
    for (int i = 0; i < 4; i++)
#pragma unroll
        for (int j = 0; j < 4; j++)
#pragma unroll
            for (int r = 0; r < 4; r++) acc[i][j][r] = 0.f;

    float4 arv[2], brv[2];

    auto ldg_stage = [&](int k0) {
#pragma unroll
        for (int p = 0; p < 2; p++) {
            int idx = p * 256 + tid;
            int r = idx >> 2, kc = (idx & 3) * 4;
            int gr = bm + r;
            arv[p] = (gr < M) ? *(const float4*)(A + (size_t)gr * K + k0 + kc)
                              : make_float4(0.f, 0.f, 0.f, 0.f);
        }
        if (TRANSB) {
#pragma unroll
            for (int p = 0; p < 2; p++) {
                int idx = p * 256 + tid;
                int r = idx >> 2, kc = (idx & 3) * 4;
                int gn = bn + r;
                brv[p] = (gn < N) ? *(const float4*)(B + (size_t)gn * K + k0 + kc)
                                  : make_float4(0.f, 0.f, 0.f, 0.f);
            }
        } else {
#pragma unroll
            for (int p = 0; p < 2; p++) {
                int idx = p * 256 + tid;
                int kr = idx >> 5, nc = (idx & 31) * 4;
                int col = bn + nc;
                const float* bp = B + (size_t)(k0 + kr) * N;
                float4 v = make_float4(0.f, 0.f, 0.f, 0.f);
                if (col + 3 < N) v = *(const float4*)(bp + col);
                else {
                    if (col + 0 < N) v.x = bp[col + 0];
                    if (col + 1 < N) v.y = bp[col + 1];
                    if (col + 2 < N) v.z = bp[col + 2];
                }
                brv[p] = v;
            }
        }
    };

    auto cvt_store = [&](const float4& v, unsigned* hi, unsigned* lo, int off) {
        unsigned hx = f2tf(v.x), hy = f2tf(v.y), hz = f2tf(v.z), hw = f2tf(v.w);
        *(uint4*)(hi + off) = make_uint4(hx, hy, hz, hw);
        if (SPLIT) {
            unsigned lx = f2tf(v.x - __uint_as_float(hx));
            unsigned ly = f2tf(v.y - __uint_as_float(hy));
            unsigned lz = f2tf(v.z - __uint_as_float(hz));
            unsigned lw = f2tf(v.w - __uint_as_float(hw));
            *(uint4*)(lo + off) = make_uint4(lx, ly, lz, lw);
        }
    };

    auto sts_stage = [&](int s) {
        unsigned* Ah = sm + s * STRIDE;
        unsigned* Al = Ah + AW;
        unsigned* Bh = sm + s * STRIDE + NBUF * AW;
        unsigned* Bl = Bh + BW;
#pragma unroll
        for (int p = 0; p < 2; p++) {
            int idx = p * 256 + tid;
            int r = idx >> 2, kc = (idx & 3) * 4;
            cvt_store(arv[p], Ah, Al, r * 20 + kc);
        }
#pragma unroll
        for (int p = 0; p < 2; p++) {
            int idx = p * 256 + tid;
            if (TRANSB) {
                int r = idx >> 2, kc = (idx & 3) * 4;
                cvt_store(brv[p], Bh, Bl, r * 20 + kc);
            } else {
                int kr = idx >> 5, nc = (idx & 31) * 4;
                cvt_store(brv[p], Bh, Bl, kr * 132 + nc);
            }
        }
    };

    auto compute = [&](int s) {
        unsigned* Ah = sm + s * STRIDE;
        unsigned* Al = Ah + AW;
        unsigned* Bh = sm + s * STRIDE + NBUF * AW;
        unsigned* Bl = Bh + BW;
#pragma unroll
        for (int kk = 0; kk < 16; kk += 8) {
            unsigned ah[4][4], al[4][4], bh[4][2], bl[4][2];
#pragma unroll
            for (int mt = 0; mt < 4; mt++) {
                int row = wm + mt * 16 + g;
                ah[mt][0] = Ah[row * 20 + kk + c4];
                ah[mt][1] = Ah[(row + 8) * 20 + kk + c4];
                ah[mt][2] = Ah[row * 20 + kk + c4 + 4];
                ah[mt][3] = Ah[(row + 8) * 20 + kk + c4 + 4];
                if (SPLIT) {
                    al[mt][0] = Al[row * 20 + kk + c4];
                    al[mt][1] = Al[(row + 8) * 20 + kk + c4];
                    al[mt][2] = Al[row * 20 + kk + c4 + 4];
                    al[mt][3] = Al[(row + 8) * 20 + kk + c4 + 4];
                }
            }
#pragma unroll
            for (int nt = 0; nt < 4; nt++) {
                int col = wn + nt * 8 + g;
                if (TRANSB) {
                    bh[nt][0] = Bh[col * 20 + kk + c4];
                    bh[nt][1] = Bh[col * 20 + kk + c4 + 4];
                    if (SPLIT) {
                        bl[nt][0] = Bl[col * 20 + kk + c4];
                        bl[nt][1] = Bl[col * 20 + kk + c4 + 4];
                    }
                } else {
                    bh[nt][0] = Bh[(kk + c4) * 132 + col];
                    bh[nt][1] = Bh[(kk + c4 + 4) * 132 + col];
                    if (SPLIT) {
                        bl[nt][0] = Bl[(kk + c4) * 132 + col];
                        bl[nt][1] = Bl[(kk + c4 + 4) * 132 + col];
                    }
                }
            }
#pragma unroll
            for (int mt = 0; mt < 4; mt++)
#pragma unroll
                for (int nt = 0; nt < 4; nt++) {
                    mma_tf32(acc[mt][nt], ah[mt][0], ah[mt][1], ah[mt][2], ah[mt][3],
                             bh[nt][0], bh[nt][1]);
                    if (SPLIT) {
                        mma_tf32(acc[mt][nt], ah[mt][0], ah[mt][1], ah[mt][2], ah[mt][3],
                                 bl[nt][0], bl[nt][1]);
                        mma_tf32(acc[mt][nt], al[mt][0], al[mt][1], al[mt][2], al[mt][3],
                                 bh[nt][0], bh[nt][1]);
                    }
                }
        }
    };

    const int KT = K / 16;
    if (STAGES == 2) {
        ldg_stage(0);
        sts_stage(0);
        __syncthreads();
        for (int kt = 0; kt < KT; ++kt) {
            if (kt + 1 < KT) ldg_stage((kt + 1) * 16);
            compute(kt & 1);
            if (kt + 1 < KT) {
                sts_stage((kt + 1) & 1);
                __syncthreads();
            }
        }
    } else {
        ldg_stage(0);
        for (int kt = 0; kt < KT; ++kt) {
            sts_stage(0);
            __syncthreads();
            if (kt + 1 < KT) ldg_stage((kt + 1) * 16);
            compute(0);
            __syncthreads();
        }
    }

    // ---- epilogue (scalar stores: C may be only 4-byte aligned) ----
    const float w = (SYM && blockIdx.x != blockIdx.y) ? 2.f : 1.f;
    float  lmn = FLT_MAX, lmx = -FLT_MAX;
    double ls = 0.0, ls2 = 0.0, lnl = 0.0;
#pragma unroll
    for (int mt = 0; mt < 4; mt++) {
#pragma unroll
        for (int nt = 0; nt < 4; nt++) {
            int col = bn + wn + nt * 8 + 2 * c4;
            bool ok0 = col < N, ok1 = col + 1 < N;
            float bias0 = 0.f, bias1 = 0.f;
            if (BIAS) { if (ok0) bias0 = bias[col]; if (ok1) bias1 = bias[col + 1]; }
#pragma unroll
            for (int half = 0; half < 2; half++) {
                int rr = bm + wm + mt * 16 + g + 8 * half;
                if (rr >= M) continue;
                float v0 = acc[mt][nt][half * 2 + 0] + bias0;
                float v1 = acc[mt][nt][half * 2 + 1] + bias1;
                if (RELU) { v0 = fmaxf(v0, 0.f); v1 = fmaxf(v1, 0.f); }
                if (STORE) {
                    if (ok0) C[(size_t)rr * N + col] = v0;
                    if (ok1) C[(size_t)rr * N + col + 1] = v1;
                }
                if (NLOSS) {
                    if (ok0) { float d = g_h[(size_t)rr * N + col] - v0;     lnl += (double)d * d; }
                    if (ok1) { float d = g_h[(size_t)rr * N + col + 1] - v1; lnl += (double)d * d; }
                }
                if (STATS) {
                    if (ok0) {
                        lmn = fminf(lmn, v0); lmx = fmaxf(lmx, v0);
                        ls += (double)(w * v0); ls2 += (double)(w * v0) * v0;
                    }
                    if (ok1) {
                        lmn = fminf(lmn, v1); lmx = fmaxf(lmx, v1);
                        ls += (double)(w * v1); ls2 += (double)(w * v1) * v1;
                    }
                }
            }
        }
    }

    if (STATS || NLOSS) {
        __syncthreads();
        double* rb = (double*)sm;
        if (NLOSS) {
            rb[tid] = lnl; __syncthreads();
            for (int o = 128; o > 0; o >>= 1) { if (tid < o) rb[tid] += rb[tid + o]; __syncthreads(); }
            if (tid == 0) atomicAdd(&g_acc[1], rb[0]);
        }
        if (STATS) {
            rb[tid] = ls; __syncthreads();
            for (int o = 128; o > 0; o >>= 1) { if (tid < o) rb[tid] += rb[tid + o]; __syncthreads(); }
            if (tid == 0) atomicAdd(&g_acc[2], rb[0]);
            __syncthreads();
            rb[tid] = ls2; __syncthreads();
            for (int o = 128; o > 0; o >>= 1) { if (tid < o) rb[tid] += rb[tid + o]; __syncthreads(); }
            if (tid == 0) atomicAdd(&g_acc[3], rb[0]);
            __syncthreads();
            float* fb = (float*)sm;
            fb[tid] = lmn; __syncthreads();
            for (int o = 128; o > 0; o >>= 1) { if (tid < o) fb[tid] = fminf(fb[tid], fb[tid + o]); __syncthreads(); }
            if (tid == 0) atomicMinF(&g_min, fb[0]);
            __syncthreads();
            fb[tid] = lmx; __syncthreads();
            for (int o = 128; o > 0; o >>= 1) { if (tid < o) fb[tid] = fmaxf(fb[tid], fb[tid + o]); __syncthreads(); }
            if (tid == 0) atomicMaxF(&g_max, fb[0]);
        }
    }
}

// ================= fp32 SIMT GEMM (head only, N=40) =================
__global__ void gemm_head(const float* __restrict__ A, const float* __restrict__ B,
                          const float* __restrict__ bias, float* __restrict__ C,
                          int M, int N, int K)
{
    __shared__ __align__(16) float As[16][64];
    __shared__ __align__(16) float Bs[16][64];
    const int tid = threadIdx.x;
    const int bm = blockIdx.y * 64, bn = blockIdx.x * 64;
    const int ty = tid >> 4, tx = tid & 15;
    float acc[4][4];
#pragma unroll
    for (int i = 0; i < 4; i++)
#pragma unroll
        for (int j = 0; j < 4; j++) acc[i][j] = 0.f;

    const int ar = tid >> 2, ac = (tid & 3) * 4;
    const int gr = bm + ar;
    for (int k0 = 0; k0 < K; k0 += 16) {
        float4 av = make_float4(0.f, 0.f, 0.f, 0.f);
        if (gr < M) av = *(const float4*)(A + (size_t)gr * K + k0 + ac);
        As[ac + 0][ar] = av.x; As[ac + 1][ar] = av.y;
        As[ac + 2][ar] = av.z; As[ac + 3][ar] = av.w;

        const int br = tid >> 4, bc = (tid & 15) * 4;
        const int gn = bn + bc;
        float4 bv = make_float4(0.f, 0.f, 0.f, 0.f);
        const float* bp = B + (size_t)(k0 + br) * N;
        if (gn + 3 < N) bv = *(const float4*)(bp + gn);
        else {
            if (gn + 0 < N) bv.x = bp[gn + 0];
            if (gn + 1 < N) bv.y = bp[gn + 1];
            if (gn + 2 < N) bv.z = bp[gn + 2];
        }
        Bs[br][bc + 0] = bv.x; Bs[br][bc + 1] = bv.y;
        Bs[br][bc + 2] = bv.z; Bs[br][bc + 3] = bv.w;
        __syncthreads();
#pragma unroll
        for (int k = 0; k < 16; k++) {
            float a[4], b[4];
            *(float4*)a = *(const float4*)&As[k][ty * 4];
            *(float4*)b = *(const float4*)&Bs[k][tx * 4];
#pragma unroll
            for (int i = 0; i < 4; i++)
#pragma unroll
                for (int j = 0; j < 4; j++) acc[i][j] = fmaf(a[i], b[j], acc[i][j]);
        }
        __syncthreads();
    }
#pragma unroll
    for (int i = 0; i < 4; i++) {
        int gm = bm + ty * 4 + i;
        if (gm >= M) continue;
#pragma unroll
        for (int j = 0; j < 4; j++) {
            int gn = bn + tx * 4 + j;
            if (gn >= N) continue;
            C[(size_t)gm * N + gn] = acc[i][j] + bias[gn];
        }
    }
}

// ---------------- aux kernels ----------------
__global__ void k_setup() {
    int i = blockIdx.x * blockDim.x + threadIdx.x;
    if (i < NNODE) { g_dego[i] = 0; g_degi[i] = 0; }
    if (blockIdx.x == 0) {
        int t = threadIdx.x;
        if (t < 8) g_acc[t] = 0.0;
        if (t == 8) g_min = __int_as_float(0x7f800000);
        if (t == 9) g_max = __int_as_float(0xff800000);
    }
}

__global__ void k_deg(const int* __restrict__ src, const int* __restrict__ dst) {
    int e = blockIdx.x * blockDim.x + threadIdx.x;
    if (e < NEDGE) {
        atomicAdd(&g_dego[src[e]], 1);
        atomicAdd(&g_degi[dst[e]], 1);
    }
}

__global__ void k_rsqrt_deg() {
    int i = blockIdx.x * blockDim.x + threadIdx.x;
    if (i < NNODE) {
        g_rso[i] = rsqrtf(fmaxf((float)g_dego[i], 1.f));
        g_rsi[i] = rsqrtf(fmaxf((float)g_degi[i], 1.f));
    }
}

// single-block scan over in-degrees -> CSR row pointers
__global__ void k_scan() {
    __shared__ int part[1024];
    int t = threadIdx.x;
    int base = t * 6;
    int loc[6]; int s = 0;
#pragma unroll
    for (int i = 0; i < 6; i++) {
        int idx = base + i; loc[i] = s;
        if (idx < NNODE) s += g_degi[idx];
    }
    part[t] = s; __syncthreads();
    for (int off = 1; off < 1024; off <<= 1) {
        int v = (t >= off) ? part[t - off] : 0;
        __syncthreads();
        part[t] += v;
        __syncthreads();
    }
    int pre = (t > 0) ? part[t - 1] : 0;
#pragma unroll
    for (int i = 0; i < 6; i++) {
        int idx = base + i;
        if (idx < NNODE) { g_rowptr[idx] = pre + loc[i]; g_cur[idx] = pre + loc[i]; }
    }
    if (t == 0) g_rowptr[NNODE] = NEDGE;
}

__global__ void k_fill(const int* __restrict__ src, const int* __restrict__ dst) {
    int e = blockIdx.x * blockDim.x + threadIdx.x;
    if (e < NEDGE) {
        int p = atomicAdd(&g_cur[dst[e]], 1);
        g_srcs[p] = src[e];
    }
}

// CSR gather-aggregate: out[n] = rsi[n] * sum_{e in in(n)} x[src(e)] * rso[src(e)]
// EDGESUM also accumulates sum_e x[dst(e)] . x[src(e)] into g_acc[4].
template <bool EDGESUM>
__global__ void k_aggregate(const float* __restrict__ x, float* __restrict__ o) {
    int n = blockIdx.x, t = threadIdx.x;   // 128 threads, DIM/4 = 128
    int beg = g_rowptr[n], end = g_rowptr[n + 1];
    float ax = 0.f, ay = 0.f, az = 0.f, aw = 0.f;
    float ux = 0.f, uy = 0.f, uz = 0.f, uw = 0.f;
    for (int e = beg; e < end; e++) {
        int s = g_srcs[e];
        float rs = g_rso[s];
        float4 v = ((const float4*)x)[(size_t)s * 128 + t];
        ax = fmaf(v.x, rs, ax); ay = fmaf(v.y, rs, ay);
        az = fmaf(v.z, rs, az); aw = fmaf(v.w, rs, aw);
        if (EDGESUM) { ux += v.x; uy += v.y; uz += v.z; uw += v.w; }
    }
    float ri = g_rsi[n];
    ((float4*)o)[(size_t)n * 128 + t] = make_float4(ax * ri, ay * ri, az * ri, aw * ri);
    if (EDGESUM) {
        float4 xn = ((const float4*)x)[(size_t)n * 128 + t];
        float part = xn.x * ux + xn.y * uy + xn.z * uz + xn.w * uw;
        __shared__ double sh[128];
        sh[t] = (double)part; __syncthreads();
        for (int off = 64; off > 0; off >>= 1) {
            if (t < off) sh[t] += sh[t + off];
            __syncthreads();
        }
        if (t == 0) atomicAdd(&g_acc[4], sh[0]);
    }
}

// row-wise L2 normalize (D=512)
__global__ void k_l2norm(const float* __restrict__ in, float* __restrict__ out) {
    int r = blockIdx.x;
    const float4* xi = (const float4*)(in + (size_t)r * DIM);
    float4* xo = (float4*)(out + (size_t)r * DIM);
    int t = threadIdx.x;
    float4 v = xi[t];
    float s = v.x * v.x + v.y * v.y + v.z * v.z + v.w * v.w;
    __shared__ float sh[128];
    sh[t] = s; __syncthreads();
    for (int o = 64; o > 0; o >>= 1) { if (t < o) sh[t] += sh[t + o]; __syncthreads(); }
    float inv = rsqrtf(sh[0] + 1e-12f);
    xo[t] = make_float4(v.x * inv, v.y * inv, v.z * inv, v.w * inv);
}

// argmax over tf32 dist with exact fp32 rescue among near-max candidates
__global__ void k_argmax(const float* __restrict__ dist, const float* __restrict__ hn,
                         const float* __restrict__ en) {
    int n = blockIdx.x, t = threadIdx.x;   // 256 threads
    const float* row = dist + (size_t)n * KC;
    float m = -3.4e38f;
    for (int j = t; j < KC; j += 256) m = fmaxf(m, row[j]);
    __shared__ float smax[256];
    smax[t] = m; __syncthreads();
    for (int o = 128; o > 0; o >>= 1) { if (t < o) smax[t] = fmaxf(smax[t], smax[t + o]); __syncthreads(); }
    float thr = smax[0] - 2.5e-4f;

    const float4* h4 = (const float4*)(hn + (size_t)n * DIM);
    float bv = -3.4e38f; int bj = KC;
    for (int j = t; j < KC; j += 256) {
        if (row[j] >= thr) {
            const float4* e4 = (const float4*)(en + (size_t)j * DIM);
            float s0 = 0.f, s1 = 0.f, s2 = 0.f, s3 = 0.f;
            for (int k = 0; k < 128; k++) {
                float4 a = h4[k], b = e4[k];
                s0 = fmaf(a.x, b.x, s0); s1 = fmaf(a.y, b.y, s1);
                s2 = fmaf(a.z, b.z, s2); s3 = fmaf(a.w, b.w, s3);
            }
            float s = (s0 + s1) + (s2 + s3);
            if (s > bv || (s == bv && j < bj)) { bv = s; bj = j; }
        }
    }
    __shared__ float sv[256];
    __shared__ int   si[256];
    sv[t] = bv; si[t] = bj; __syncthreads();
    for (int o = 128; o > 0; o >>= 1) {
        if (t < o) {
            float v2 = sv[t + o]; int i2 = si[t + o];
            if (v2 > sv[t] || (v2 == sv[t] && i2 < si[t])) { sv[t] = v2; si[t] = i2; }
        }
        __syncthreads();
    }
    if (t == 0) g_ind[n] = si[0];
}

__global__ void k_gather_commit() {
    int n = blockIdx.x;
    int idx = g_ind[n];
    const float4* e = (const float4*)(g_en + (size_t)idx * DIM);
    const float4* h = (const float4*)(g_h + (size_t)n * DIM);
    float4* q = (float4*)(g_q + (size_t)n * DIM);
    int t = threadIdx.x;
    float4 ev = e[t], hv = h[t];
    q[t] = ev;
    float dx = ev.x - hv.x, dy = ev.y - hv.y, dz = ev.z - hv.z, dw = ev.w - hv.w;
    double s = (double)dx * dx + (double)dy * dy + (double)dz * dz + (double)dw * dw;
    __shared__ double sh[128];
    sh[t] = s; __syncthreads();
    for (int o = 64; o > 0; o >>= 1) { if (t < o) sh[t] += sh[t + o]; __syncthreads(); }
    if (t == 0) atomicAdd(&g_acc[0], sh[0]);
}

// duplicate-edge multiplicity: sum over CSR rows of #{(i,j) : src_i == src_j} = sum_distinct c^2
__global__ void k_dup() {
    int n = blockIdx.x;
    int beg = g_rowptr[n], end = g_rowptr[n + 1];
    int L = end - beg;
    __shared__ int srow[1024];
    bool cached = (L <= 1024);
    if (cached)
        for (int i = threadIdx.x; i < L; i += blockDim.x) srow[i] = g_srcs[beg + i];
    __syncthreads();
    int cnt = 0;
    for (int i = 0; i < L; i++) {
        int si = cached ? srow[i] : g_srcs[beg + i];
        for (int j = threadIdx.x; j < L; j += blockDim.x) {
            int sj = cached ? srow[j] : g_srcs[beg + j];
            cnt += (si == sj);
        }
    }
    __shared__ int sc[128];
    sc[threadIdx.x] = cnt; __syncthreads();
    for (int o = 64; o > 0; o >>= 1) {
        if (threadIdx.x < o) sc[threadIdx.x] += sc[threadIdx.x + o];
        __syncthreads();
    }
    if (threadIdx.x == 0) atomicAdd(&g_acc[5], (double)sc[0]);
}

__global__ void k_final(float* __restrict__ loss) {
    double nd = (double)NNODE * DIM;
    double commit = 0.25 * g_acc[0] / nd;
    double nodeL  = g_acc[1] / nd;
    double mn = (double)g_min, mx = (double)g_max;
    double inv = 1.0 / (mx - mn);
    double NN = (double)NNODE * (double)NNODE;
    double Sa2 = inv * inv * (g_acc[3] - 2.0 * mn * g_acc[2] + NN * mn * mn);
    double Sea = inv * (g_acc[4] - (double)NEDGE * mn);
    double tot = Sa2 - 2.0 * Sea + g_acc[5];
    double edgeL = sqrt(tot / NN);
    *loss = (float)(nodeL + edgeL + commit);
}

// ---------------- launch ----------------
extern "C" void kernel_launch(void* const* d_in, const int* in_sizes, int n_in,
                              void* d_out, int out_size) {
    (void)in_sizes; (void)n_in; (void)out_size;
    const float* feats = (const float*)d_in[0];
    const float* W1  = (const float*)d_in[1];
    const float* b1  = (const float*)d_in[2];
    const float* W2  = (const float*)d_in[3];
    const float* b2  = (const float*)d_in[4];
    const float* Wd1 = (const float*)d_in[5];
    const float* bd1 = (const float*)d_in[6];
    const float* Wd2 = (const float*)d_in[7];
    const float* bd2 = (const float*)d_in[8];
    const float* Wl  = (const float*)d_in[9];
    const float* bl  = (const float*)d_in[10];
    const float* cb  = (const float*)d_in[11];
    const int* src   = (const int*)d_in[12];
    const int* dst   = (const int*)d_in[13];

    float* out  = (float*)d_out;
    float* loss = out + (size_t)NNODE * NOUT;
    float* dist = loss + 1;

    float *p_h, *p_agg, *p_hn, *p_en, *p_q, *p_xe, *p_h2;
    cudaGetSymbolAddress((void**)&p_h,   g_h);
    cudaGetSymbolAddress((void**)&p_agg, g_agg);
    cudaGetSymbolAddress((void**)&p_hn,  g_hn);
    cudaGetSymbolAddress((void**)&p_en,  g_en);
    cudaGetSymbolAddress((void**)&p_q,   g_q);
    cudaGetSymbolAddress((void**)&p_xe,  g_xe);
    cudaGetSymbolAddress((void**)&p_h2,  g_h2);

    #define TGRID(M, N) dim3(((N) + 127) / 128, ((M) + 127) / 128)

    k_setup<<<(NNODE + 255) / 256, 256>>>();
    k_deg<<<(NEDGE + 255) / 256, 256>>>(src, dst);
    k_rsqrt_deg<<<(NNODE + 255) / 256, 256>>>();
    k_scan<<<1, 1024>>>();
    k_fill<<<(NEDGE + 255) / 256, 256>>>(src, dst);

    // GraphConv 1 (split precision: feeds dist/out paths)
    k_aggregate<false><<<NNODE, 128>>>(feats, p_agg);
    tgemm<false, true, true, false, true, true, false, false><<<TGRID(NNODE, DIM), 256>>>(
        p_agg, W1, b1, p_h, NNODE, DIM, DIM);

    // VQ: dist in plain tf32 (2-stage pipelined) + exact-fp32 argmax rescue
    k_l2norm<<<KC, 128>>>(cb, p_en);
    k_l2norm<<<NNODE, 128>>>(p_h, p_hn);
    tgemm<true, false, false, false, false, true, false, false><<<TGRID(NNODE, KC), 256>>>(
        p_hn, p_en, nullptr, dist, NNODE, KC, DIM);
    k_argmax<<<NNODE, 256>>>(dist, p_hn, p_en);
    k_gather_commit<<<NNODE, 128>>>();

    // decoders: xe feeds out path (split); qn is loss-only -> fused node-loss, no store
    tgemm<false, false, true, false, true, true, false, false><<<TGRID(NNODE, DIM), 256>>>(
        p_q, Wd1, bd1, p_xe, NNODE, DIM, DIM);
    tgemm<false, false, true, false, false, false, false, true><<<TGRID(NNODE, DIM), 256>>>(
        p_q, Wd2, bd2, nullptr, NNODE, DIM, DIM);

    // adjacency reconstruction: symmetric stats-only GEMM (upper-tri tiles), dup counts
    tgemm<true, false, false, true, false, false, true, false><<<TGRID(NNODE, NNODE), 256>>>(
        p_xe, p_xe, nullptr, nullptr, NNODE, NNODE, DIM);
    k_dup<<<NNODE, 128>>>();

    // GraphConv 2 (aggregate fused with edge-sum) + head
    k_aggregate<true><<<NNODE, 128>>>(p_xe, p_agg);
    tgemm<false, true, true, false, true, true, false, false><<<TGRID(NNODE, DIM), 256>>>(
        p_agg, W2, b2, p_h2, NNODE, DIM, DIM);
    gemm_head<<<dim3(1, (NNODE + 63) / 64), 256>>>(p_h2, Wl, bl, out, NNODE, NOUT, DIM);

    k_final<<<1, 1>>>(loss);
    #undef TGRID
}